// round 3
// baseline (speedup 1.0000x reference)
#include <cuda_runtime.h>
#include <cuda_bf16.h>
#include <math.h>
#include <stdint.h>

#define NN 60000
#define EE 300000
#define AA 8000
#define GG 256
#define DD 128
#define HH 8
#define CC 16
#define RBFD 16
#define SBFD 112
#define LLAYERS 3

// ---------------- scratch (device globals; no allocation allowed) ----------------
__device__ float g_cur [NN*DD];
__device__ float g_hbuf[NN*DD];
__device__ float g_t1  [NN*DD];
__device__ float g_t2  [NN*DD];
__device__ float g_q   [NN*DD];
__device__ float g_k   [NN*DD];
__device__ float g_v   [NN*DD];
__device__ float g_eaA [EE*DD];
__device__ float g_eaB [EE*DD];
__device__ float g_atoms [AA*DD];
__device__ float g_atoms2[AA*DD];
__device__ float g_a1  [AA*DD];
__device__ float g_a2  [AA*DD];
__device__ float g_logit[EE*HH];
__device__ unsigned g_m[NN*HH];
__device__ float g_den [NN*HH];
__device__ float g_results[AA];
__device__ float g_gstat[5*GG];

// ---------------- helpers ----------------
__device__ __forceinline__ float siluf(float v){ return v * (1.f / (1.f + __expf(-v))); }
__device__ __forceinline__ unsigned f2o(float f){ unsigned u=__float_as_uint(f); return (u&0x80000000u)? ~u : (u|0x80000000u); }
__device__ __forceinline__ float o2f(unsigned u){ return (u&0x80000000u)? __uint_as_float(u^0x80000000u) : __uint_as_float(~u); }

__device__ __forceinline__ uint32_t smem_u32(const void* p){
    uint32_t a;
    asm("{ .reg .u64 t; cvta.to.shared.u64 t, %1; cvt.u32.u64 %0, t; }" : "=r"(a) : "l"(p));
    return a;
}
__device__ __forceinline__ void ldm4(uint32_t* r, uint32_t addr){
    asm volatile("ldmatrix.sync.aligned.m8n8.x4.shared.b16 {%0,%1,%2,%3}, [%4];"
        : "=r"(r[0]),"=r"(r[1]),"=r"(r[2]),"=r"(r[3]) : "r"(addr));
}
__device__ __forceinline__ void mma16816(float* c, const uint32_t* a, const uint32_t* b){
    asm volatile("mma.sync.aligned.m16n8k16.row.col.f32.bf16.bf16.f32 "
        "{%0,%1,%2,%3}, {%4,%5,%6,%7}, {%8,%9}, {%0,%1,%2,%3};"
        : "+f"(c[0]),"+f"(c[1]),"+f"(c[2]),"+f"(c[3])
        : "r"(a[0]),"r"(a[1]),"r"(a[2]),"r"(a[3]), "r"(b[0]),"r"(b[1]));
}
__device__ __forceinline__ void split_bf16(float v, __nv_bfloat16& h, __nv_bfloat16& l){
    h = __float2bfloat16(v);
    l = __float2bfloat16(v - __bfloat162float(h));
}

// smem layout (bf16, padded stride 136 elems = 272B for conflict-free ldmatrix)
#define STRD 136
#define OFF_WHI 0
#define OFF_WLO 34816
#define OFF_AHI 69632
#define OFF_ALO 104448
static constexpr int SMEM_T = 139264;

// ---------------- bf16x2-split tensor-core GEMM ----------------
// C[M,128] = epi(A'[M,K] @ W[K,128] + bias);  A'[m,:] = A[gidx[m],:] if GATHER
template<int ACT, bool GATHER, bool HASRES, int K>
__global__ __launch_bounds__(256)
void gemm_mma(const float* __restrict__ A, const float* __restrict__ W,
              const float* __restrict__ bias, const float* __restrict__ res,
              const int* __restrict__ gidx, float* __restrict__ C, int M)
{
    extern __shared__ __align__(128) char smem[];
    __nv_bfloat16* Whi = (__nv_bfloat16*)(smem + OFF_WHI);
    __nv_bfloat16* Wlo = (__nv_bfloat16*)(smem + OFF_WLO);
    const int tid = threadIdx.x;
    const int lane = tid & 31, w = tid >> 5;
    const int row0 = blockIdx.x * 128;

    // ---- W -> smem transposed [n][k], hi/lo ----
    for (int idx = tid; idx < 128*128; idx += 256){
        int k = idx >> 7, n = idx & 127;
        float wv = (k < K) ? __ldg(W + (size_t)k*128 + n) : 0.f;
        __nv_bfloat16 h, l; split_bf16(wv, h, l);
        Whi[n*STRD + k] = h;
        Wlo[n*STRD + k] = l;
    }
    // ---- A tile -> smem [m][k], hi/lo ----
    for (int idx = tid; idx < 128*64; idx += 256){
        int r = idx >> 6, k = (idx & 63) * 2;
        float2 v = make_float2(0.f, 0.f);
        int gr = row0 + r;
        if (gr < M && k < K){
            int ar = GATHER ? __ldg(gidx + gr) : gr;
            v = *reinterpret_cast<const float2*>(A + (size_t)ar*K + k);
        }
        __nv_bfloat16 h0,l0,h1,l1;
        split_bf16(v.x, h0, l0); split_bf16(v.y, h1, l1);
        uint32_t hp = ((uint32_t)__bfloat16_as_ushort(h1)<<16) | __bfloat16_as_ushort(h0);
        uint32_t lp = ((uint32_t)__bfloat16_as_ushort(l1)<<16) | __bfloat16_as_ushort(l0);
        *(uint32_t*)(smem + OFF_AHI + (r*STRD + k)*2) = hp;
        *(uint32_t*)(smem + OFF_ALO + (r*STRD + k)*2) = lp;
    }
    __syncthreads();

    const int m_warp = (w >> 2) * 64;   // 0 / 64
    const int n_warp = (w & 3) * 32;    // 0,32,64,96
    const uint32_t sb = smem_u32(smem);
    const uint32_t aHi = sb + OFF_AHI, aLo = sb + OFF_ALO;
    const uint32_t wHi = sb + OFF_WHI, wLo = sb + OFF_WLO;

    const int a_rin = lane & 15;
    const int a_kad = (lane >> 4) << 3;
    const int b_nin = (lane & 7) + ((lane & 16) ? 8 : 0);
    const int b_kad = (lane & 8);

    float c[64];
    #pragma unroll
    for (int i = 0; i < 64; i++) c[i] = 0.f;

    #pragma unroll
    for (int ks = 0; ks < 8; ks++){
        const int k0 = ks * 16;
        uint32_t bh[8], bl[8];
        #pragma unroll
        for (int g = 0; g < 2; g++){
            uint32_t off = ((uint32_t)(n_warp + g*16 + b_nin) * STRD + k0 + b_kad) * 2;
            ldm4(&bh[g*4], wHi + off);
            ldm4(&bl[g*4], wLo + off);
        }
        uint32_t ah[16], al[16];
        #pragma unroll
        for (int mt = 0; mt < 4; mt++){
            uint32_t off = ((uint32_t)(m_warp + mt*16 + a_rin) * STRD + k0 + a_kad) * 2;
            ldm4(&ah[mt*4], aHi + off);
            ldm4(&al[mt*4], aLo + off);
        }
        #pragma unroll
        for (int mt = 0; mt < 4; mt++){
            #pragma unroll
            for (int nt = 0; nt < 4; nt++){
                float* cp = &c[(mt*4 + nt)*4];
                mma16816(cp, &ah[mt*4], &bh[nt*2]);
                mma16816(cp, &ah[mt*4], &bl[nt*2]);
                mma16816(cp, &al[mt*4], &bh[nt*2]);
            }
        }
    }

    // ---- epilogue from fragments ----
    #pragma unroll
    for (int mt = 0; mt < 4; mt++){
        #pragma unroll
        for (int nt = 0; nt < 4; nt++){
            const float* cp = &c[(mt*4 + nt)*4];
            int cb = n_warp + nt*8 + 2*(lane & 3);
            float2 bb = make_float2(0.f, 0.f);
            if (bias) bb = *reinterpret_cast<const float2*>(bias + cb);
            #pragma unroll
            for (int hh = 0; hh < 2; hh++){
                int gr = row0 + m_warp + mt*16 + (lane >> 2) + hh*8;
                if (gr >= M) continue;
                float v0 = cp[hh*2+0] + bb.x;
                float v1 = cp[hh*2+1] + bb.y;
                if (ACT==1){ v0 = siluf(v0); v1 = siluf(v1); }
                if (HASRES){
                    float2 rr = *reinterpret_cast<const float2*>(res + (size_t)gr*128 + cb);
                    v0 += rr.x; v1 += rr.y;
                }
                *reinterpret_cast<float2*>(C + (size_t)gr*128 + cb) = make_float2(v0, v1);
            }
        }
    }
}

// ---------------- scatter rows: dst[idx[n],:] += src[n,:] ----------------
__global__ void scatter_rows_kernel(const float* __restrict__ src, const int* __restrict__ idx,
                                    float* __restrict__ dstb, int nrows)
{
    int i = blockIdx.x*blockDim.x + threadIdx.x;
    if (i >= nrows*32) return;
    int n = i >> 5, c4 = i & 31;
    int a = __ldg(idx + n);
    float4 v = *reinterpret_cast<const float4*>(src + (size_t)n*128 + c4*4);
    float* d = dstb + (size_t)a*128 + c4*4;
    atomicAdd(d+0,v.x); atomicAdd(d+1,v.y); atomicAdd(d+2,v.z); atomicAdd(d+3,v.w);
}

// ---------------- rbf gate: h[n,c] *= (rbf[n,:] @ W[:,c]) ----------------
__global__ void gate_mul_kernel(float* __restrict__ h, const float* __restrict__ rbf,
                                const float* __restrict__ W)
{
    __shared__ float Ws[RBFD][DD];
    for (int t=threadIdx.x; t<RBFD*DD; t+=256) ((float*)Ws)[t] = W[t];
    __syncthreads();
    int c   = threadIdx.x & 127;
    int sub = threadIdx.x >> 7;
    int n0  = blockIdx.x*128;
    int nend = min(n0+128, NN);
    for (int n = n0+sub; n < nend; n += 2){
        const float* r = rbf + (size_t)n*RBFD;
        float g = 0.f;
        #pragma unroll
        for (int kk=0;kk<RBFD;kk++) g = fmaf(__ldg(r+kk), Ws[kk][c], g);
        h[(size_t)n*DD+c] *= g;
    }
}

// ---------------- readout gate + scatter ----------------
__global__ void gate_scatter_kernel(const float* __restrict__ h, const float* __restrict__ rbf,
                                    const float* __restrict__ W, const int* __restrict__ idx,
                                    float* __restrict__ atoms)
{
    __shared__ float Ws[RBFD][DD];
    for (int t=threadIdx.x; t<RBFD*DD; t+=256) ((float*)Ws)[t] = W[t];
    __syncthreads();
    int c   = threadIdx.x & 127;
    int sub = threadIdx.x >> 7;
    int n0  = blockIdx.x*128;
    int nend = min(n0+128, NN);
    for (int n = n0+sub; n < nend; n += 2){
        const float* r = rbf + (size_t)n*RBFD;
        float g = 0.f;
        #pragma unroll
        for (int kk=0;kk<RBFD;kk++) g = fmaf(__ldg(r+kk), Ws[kk][c], g);
        atomicAdd(&atoms[(size_t)__ldg(idx+n)*DD + c], h[(size_t)n*DD+c]*g);
    }
}

// ---------------- attention: logits + running max ----------------
__global__ void logit_kernel(const float* __restrict__ q, const float* __restrict__ k,
                             const float* __restrict__ ek, const int* __restrict__ src,
                             const int* __restrict__ dst, float* __restrict__ logit,
                             unsigned* __restrict__ mOrd)
{
    int i = blockIdx.x*blockDim.x + threadIdx.x;
    if (i >= EE*HH) return;
    int e = i >> 3, h = i & 7;
    int s = __ldg(src+e), d = __ldg(dst+e);
    const float4* qp = (const float4*)(q  + (size_t)d*DD + h*CC);
    const float4* kp = (const float4*)(k  + (size_t)s*DD + h*CC);
    const float4* ep = (const float4*)(ek + (size_t)e*DD + h*CC);
    float acc = 0.f;
    #pragma unroll
    for (int j=0;j<4;j++){
        float4 a=qp[j], b=kp[j], c=ep[j];
        acc += a.x*(b.x+c.x)+a.y*(b.y+c.y)+a.z*(b.z+c.z)+a.w*(b.w+c.w);
    }
    acc *= 0.25f;
    logit[i] = acc;
    atomicMax(&mOrd[(size_t)d*HH+h], f2o(acc));
}

// ---------------- attention: exp + denominator ----------------
__global__ void exp_kernel(const int* __restrict__ dst, float* __restrict__ logit,
                           const unsigned* __restrict__ mOrd, float* __restrict__ den)
{
    int i = blockIdx.x*blockDim.x + threadIdx.x;
    if (i >= EE*HH) return;
    int e = i >> 3, h = i & 7;
    int d = __ldg(dst+e);
    float m  = o2f(mOrd[(size_t)d*HH+h]);
    float ex = __expf(logit[i] - m);
    logit[i] = ex;
    atomicAdd(&den[(size_t)d*HH+h], ex);
}

// ---------------- attention: weighted message scatter ----------------
__global__ void msg_kernel(const float* __restrict__ v, const float* __restrict__ ek,
                           const float* __restrict__ sw, const float* __restrict__ ex,
                           const float* __restrict__ den, const int* __restrict__ src,
                           const int* __restrict__ dst, float* __restrict__ hout)
{
    int i = blockIdx.x*blockDim.x + threadIdx.x;
    if (i >= EE*32) return;
    int e = i >> 5, c4 = i & 31, h = c4 >> 2;
    int sN = __ldg(src+e), dN = __ldg(dst+e);
    float alpha = __ldg(ex + (size_t)e*HH + h) / (__ldg(den + (size_t)dN*HH + h) + 1e-16f);
    float4 vv = *(const float4*)(v  + (size_t)sN*DD + c4*4);
    float4 ee = *(const float4*)(ek + (size_t)e*DD  + c4*4);
    float4 ww = *(const float4*)(sw + (size_t)e*DD  + c4*4);
    float* o = hout + (size_t)dN*DD + c4*4;
    atomicAdd(o+0, (vv.x+ee.x)*alpha*ww.x);
    atomicAdd(o+1, (vv.y+ee.y)*alpha*ww.y);
    atomicAdd(o+2, (vv.z+ee.z)*alpha*ww.z);
    atomicAdd(o+3, (vv.w+ee.w)*alpha*ww.w);
}

// ---------------- graph norm ----------------
__global__ void gn_pass1_kernel(const float* __restrict__ h, const int* __restrict__ batch,
                                float* __restrict__ gstat)
{
    int gi = blockIdx.x*blockDim.x + threadIdx.x;
    int n = gi >> 5, lane = gi & 31;
    if (n >= NN) return;
    float4 v = *reinterpret_cast<const float4*>(h + (size_t)n*128 + lane*4);
    float s = v.x+v.y+v.z+v.w;
    #pragma unroll
    for(int o=16;o;o>>=1) s += __shfl_xor_sync(0xffffffffu, s, o);
    if (!lane){
        int g = __ldg(batch+n);
        atomicAdd(&gstat[g], s);
        atomicAdd(&gstat[GG+g], 1.f);
    }
}
__global__ void gn_mean_kernel(float* gstat)
{
    int g = threadIdx.x;
    if (g >= GG) return;
    float cnt = gstat[GG+g]*128.f;
    gstat[2*GG+g] = (cnt > 0.f) ? gstat[g]/cnt : 0.f;
}
__global__ void gn_pass2_kernel(const float* __restrict__ h, const int* __restrict__ batch,
                                float* __restrict__ gstat)
{
    int gi = blockIdx.x*blockDim.x + threadIdx.x;
    int n = gi >> 5, lane = gi & 31;
    if (n >= NN) return;
    int g = __ldg(batch+n);
    float mean = gstat[2*GG+g];
    float4 v = *reinterpret_cast<const float4*>(h + (size_t)n*128 + lane*4);
    float a=v.x-mean, b=v.y-mean, c=v.z-mean, d=v.w-mean;
    float s = a*a+b*b+c*c+d*d;
    #pragma unroll
    for(int o=16;o;o>>=1) s += __shfl_xor_sync(0xffffffffu, s, o);
    if (!lane) atomicAdd(&gstat[3*GG+g], s);
}
__global__ void gn_rstd_kernel(float* gstat)
{
    int g = threadIdx.x;
    if (g >= GG) return;
    float cnt = gstat[GG+g]*128.f;
    float var = (cnt > 0.f) ? gstat[3*GG+g]/cnt : 0.f;
    gstat[4*GG+g] = rsqrtf(var + 1e-8f);
}
__global__ void gn_apply_kernel(float* __restrict__ h, const int* __restrict__ batch,
                                const float* __restrict__ gstat)
{
    int i = blockIdx.x*blockDim.x + threadIdx.x;
    if (i >= NN*32) return;
    int n = i >> 5;
    int g = __ldg(batch+n);
    float mean = gstat[2*GG+g], rstd = gstat[4*GG+g];
    float4 v = *reinterpret_cast<const float4*>(h + (size_t)n*128 + (i&31)*4);
    v.x=(v.x-mean)*rstd; v.y=(v.y-mean)*rstd; v.z=(v.z-mean)*rstd; v.w=(v.w-mean)*rstd;
    *reinterpret_cast<float4*>(h + (size_t)n*128 + (i&31)*4) = v;
}

// ---------------- readout final dot ----------------
__global__ void readout_dot_kernel(const float* __restrict__ a2, const float* __restrict__ w3,
                                   const float* __restrict__ b3, float* __restrict__ results)
{
    int gi = blockIdx.x*blockDim.x + threadIdx.x;
    int a = gi >> 5, lane = gi & 31;
    if (a >= AA) return;
    float4 x = *(const float4*)(a2 + (size_t)a*128 + lane*4);
    float4 w = *(const float4*)(w3 + lane*4);
    float s = x.x*w.x + x.y*w.y + x.z*w.z + x.w*w.w;
    #pragma unroll
    for(int o=16;o;o>>=1) s += __shfl_xor_sync(0xffffffffu, s, o);
    if (!lane) results[a] += s + __ldg(b3);
}

// ---------------- final: out[g] = sum_a results[a] / 3 ----------------
__global__ void final_kernel(const float* __restrict__ results, const int* __restrict__ atom_batch,
                             float* __restrict__ out)
{
    int a = blockIdx.x*blockDim.x + threadIdx.x;
    if (a < AA) atomicAdd(&out[__ldg(atom_batch+a)], results[a]*(1.f/3.f));
}

// =======================================================================
extern "C" void kernel_launch(void* const* d_in, const int* in_sizes, int n_in,
                              void* d_out, int out_size)
{
    cudaStream_t s = 0;
    const float* x            = (const float*)d_in[0];
    const float* node_rbf     = (const float*)d_in[1];
    const float* edge_sbf     = (const float*)d_in[2];
    const int*   edge_index   = (const int*)  d_in[3];
    const int*   srcp = edge_index;
    const int*   dstp = edge_index + EE;
    const int*   pair_atom_idx= (const int*)  d_in[4];
    const int*   edge_index_0 = (const int*)  d_in[5];
    const int*   atom_batch   = (const int*)  d_in[6];
    const int*   batch        = (const int*)  d_in[7];
    const float* edgenn_w1    = (const float*)d_in[8];
    const float* edgenn_b1    = (const float*)d_in[9];
    const float* edgenn_w2    = (const float*)d_in[10];
    const float* edgenn_b2    = (const float*)d_in[11];
    const float* conv_wq      = (const float*)d_in[12];
    const float* conv_wk      = (const float*)d_in[13];
    const float* conv_wv      = (const float*)d_in[14];
    const float* conv_we      = (const float*)d_in[15];
    const float* conv_wsbf    = (const float*)d_in[16];
    const float* conv_bsbf    = (const float*)d_in[17];
    const float* conv_wrbf    = (const float*)d_in[18];
    const float* dense_w      = (const float*)d_in[19];
    const float* dense_b      = (const float*)d_in[20];
    const float* bf_w         = (const float*)d_in[21];
    const float* bf_b         = (const float*)d_in[22];
    const float* af_w         = (const float*)d_in[23];
    const float* af_b         = (const float*)d_in[24];
    const float* read_wrbf    = (const float*)d_in[25];
    const float* read_w1      = (const float*)d_in[26];
    const float* read_b1      = (const float*)d_in[27];
    const float* read_w2      = (const float*)d_in[28];
    const float* read_b2      = (const float*)d_in[29];
    const float* read_w3      = (const float*)d_in[30];
    const float* read_b3      = (const float*)d_in[31];

    cudaFuncSetAttribute((void*)gemm_mma<1,true ,false,128>, cudaFuncAttributeMaxDynamicSharedMemorySize, SMEM_T);
    cudaFuncSetAttribute((void*)gemm_mma<0,false,false,128>, cudaFuncAttributeMaxDynamicSharedMemorySize, SMEM_T);
    cudaFuncSetAttribute((void*)gemm_mma<1,false,false,128>, cudaFuncAttributeMaxDynamicSharedMemorySize, SMEM_T);
    cudaFuncSetAttribute((void*)gemm_mma<1,false,true ,128>, cudaFuncAttributeMaxDynamicSharedMemorySize, SMEM_T);
    cudaFuncSetAttribute((void*)gemm_mma<0,false,false,112>, cudaFuncAttributeMaxDynamicSharedMemorySize, SMEM_T);

    float *cur_w, *hbuf, *t1, *t2, *q, *k_, *v_, *eaA, *eaB;
    float *atoms, *atoms2, *a1, *a2, *logit, *den, *results, *gstat;
    unsigned* mOrd;
    cudaGetSymbolAddress((void**)&cur_w,  g_cur);
    cudaGetSymbolAddress((void**)&hbuf,   g_hbuf);
    cudaGetSymbolAddress((void**)&t1,     g_t1);
    cudaGetSymbolAddress((void**)&t2,     g_t2);
    cudaGetSymbolAddress((void**)&q,      g_q);
    cudaGetSymbolAddress((void**)&k_,     g_k);
    cudaGetSymbolAddress((void**)&v_,     g_v);
    cudaGetSymbolAddress((void**)&eaA,    g_eaA);
    cudaGetSymbolAddress((void**)&eaB,    g_eaB);
    cudaGetSymbolAddress((void**)&atoms,  g_atoms);
    cudaGetSymbolAddress((void**)&atoms2, g_atoms2);
    cudaGetSymbolAddress((void**)&a1,     g_a1);
    cudaGetSymbolAddress((void**)&a2,     g_a2);
    cudaGetSymbolAddress((void**)&logit,  g_logit);
    cudaGetSymbolAddress((void**)&mOrd,   g_m);
    cudaGetSymbolAddress((void**)&den,    g_den);
    cudaGetSymbolAddress((void**)&results,g_results);
    cudaGetSymbolAddress((void**)&gstat,  g_gstat);

    auto gemmL = [&](const float* A, const float* Wp, const float* bp, const float* rp,
                     const int* gi, float* Cp, int M, int K, int act){
        int grid = (M + 127) / 128;
        if (K == 112)        gemm_mma<0,false,false,112><<<grid,256,SMEM_T,s>>>(A,Wp,bp,rp,gi,Cp,M);
        else if (gi)         gemm_mma<1,true ,false,128><<<grid,256,SMEM_T,s>>>(A,Wp,bp,rp,gi,Cp,M);
        else if (act && rp)  gemm_mma<1,false,true ,128><<<grid,256,SMEM_T,s>>>(A,Wp,bp,rp,gi,Cp,M);
        else if (act)        gemm_mma<1,false,false,128><<<grid,256,SMEM_T,s>>>(A,Wp,bp,rp,gi,Cp,M);
        else                 gemm_mma<0,false,false,128><<<grid,256,SMEM_T,s>>>(A,Wp,bp,rp,gi,Cp,M);
    };

    auto readout = [&](int i, const float* h){
        cudaMemsetAsync(atoms2, 0, (size_t)AA*DD*4, s);
        gate_scatter_kernel<<<(NN+127)/128, 256, 0, s>>>(
            h, node_rbf, read_wrbf + (size_t)i*RBFD*DD, edge_index_0, atoms2);
        gemmL(atoms2, read_w1 + (size_t)i*DD*DD, read_b1 + (size_t)i*DD, nullptr, nullptr, a1, AA, DD, 1);
        gemmL(a1,     read_w2 + (size_t)i*DD*DD, read_b2 + (size_t)i*DD, nullptr, nullptr, a2, AA, DD, 1);
        readout_dot_kernel<<<(AA*32+255)/256, 256, 0, s>>>(
            a2, read_w3 + (size_t)i*DD, read_b3 + i, results);
    };

    // ---- init ----
    cudaMemsetAsync(results, 0, (size_t)AA*4, s);
    readout(0, x);
    const float* cur = x;

    for (int i = 0; i < LLAYERS; i++){
        size_t wDD  = (size_t)i*DD*DD;
        cudaMemsetAsync(atoms, 0, (size_t)AA*DD*4, s);
        scatter_rows_kernel<<<(NN*32+255)/256, 256, 0, s>>>(cur, edge_index_0, atoms, NN);
        gemmL(atoms, edgenn_w1 + wDD, edgenn_b1 + (size_t)i*DD, nullptr, pair_atom_idx, eaA, EE, DD, 1);
        gemmL(eaA,   edgenn_w2 + wDD, edgenn_b2 + (size_t)i*DD, nullptr, nullptr,       eaB, EE, DD, 0);
        gemmL(cur, conv_wq + wDD, nullptr, nullptr, nullptr, q,  NN, DD, 0);
        gemmL(cur, conv_wk + wDD, nullptr, nullptr, nullptr, k_, NN, DD, 0);
        gemmL(cur, conv_wv + wDD, nullptr, nullptr, nullptr, v_, NN, DD, 0);
        gemmL(eaB, conv_we + wDD, nullptr, nullptr, nullptr, eaA, EE, DD, 0);
        gemmL(edge_sbf, conv_wsbf + (size_t)i*SBFD*DD, conv_bsbf + (size_t)i*DD,
              nullptr, nullptr, eaB, EE, SBFD, 0);
        cudaMemsetAsync(mOrd, 0, (size_t)NN*HH*4, s);
        cudaMemsetAsync(den,  0, (size_t)NN*HH*4, s);
        logit_kernel<<<(EE*HH+255)/256, 256, 0, s>>>(q, k_, eaA, srcp, dstp, logit, mOrd);
        exp_kernel  <<<(EE*HH+255)/256, 256, 0, s>>>(dstp, logit, mOrd, den);
        cudaMemsetAsync(hbuf, 0, (size_t)NN*DD*4, s);
        msg_kernel  <<<(EE*32+255)/256, 256, 0, s>>>(v_, eaA, eaB, logit, den, srcp, dstp, hbuf);
        gate_mul_kernel<<<(NN+127)/128, 256, 0, s>>>(hbuf, node_rbf, conv_wrbf + (size_t)i*RBFD*DD);
        cudaMemsetAsync(gstat, 0, 5*GG*4, s);
        gn_pass1_kernel<<<(NN*32+255)/256, 256, 0, s>>>(hbuf, batch, gstat);
        gn_mean_kernel <<<1, GG, 0, s>>>(gstat);
        gn_pass2_kernel<<<(NN*32+255)/256, 256, 0, s>>>(hbuf, batch, gstat);
        gn_rstd_kernel <<<1, GG, 0, s>>>(gstat);
        gn_apply_kernel<<<(NN*32+255)/256, 256, 0, s>>>(hbuf, batch, gstat);
        gemmL(hbuf, bf_w + (size_t)i*2*DD*DD,          bf_b + (size_t)i*2*DD,      nullptr, nullptr, t1, NN, DD, 1);
        gemmL(t1,   bf_w + (size_t)i*2*DD*DD + DD*DD,  bf_b + (size_t)i*2*DD + DD, hbuf,    nullptr, t2, NN, DD, 1);
        gemmL(t2, dense_w + wDD, dense_b + (size_t)i*DD, cur, nullptr, t1, NN, DD, 1);
        gemmL(t1, af_w + (size_t)i*4*DD*DD,           af_b + (size_t)i*4*DD,        nullptr, nullptr, q,  NN, DD, 1);
        gemmL(q,  af_w + (size_t)i*4*DD*DD + 1*DD*DD, af_b + (size_t)i*4*DD + DD,   t1,      nullptr, t2, NN, DD, 1);
        gemmL(t2, af_w + (size_t)i*4*DD*DD + 2*DD*DD, af_b + (size_t)i*4*DD + 2*DD, nullptr, nullptr, q,     NN, DD, 1);
        gemmL(q,  af_w + (size_t)i*4*DD*DD + 3*DD*DD, af_b + (size_t)i*4*DD + 3*DD, t2,      nullptr, cur_w, NN, DD, 1);
        cur = cur_w;
        readout(i+1, cur);
    }

    cudaMemsetAsync(d_out, 0, (size_t)GG*4, s);
    final_kernel<<<(AA+255)/256, 256, 0, s>>>(results, atom_batch, (float*)d_out);
}

// round 4
// speedup vs baseline: 1.3966x; 1.3966x over previous
#include <cuda_runtime.h>
#include <cuda_bf16.h>
#include <math.h>
#include <stdint.h>

#define NN 60000
#define EE 300000
#define AA 8000
#define GG 256
#define DD 128
#define HH 8
#define CC 16
#define RBFD 16
#define SBFD 112
#define LLAYERS 3

// ---------------- fp32 scratch ----------------
__device__ float g_cur [NN*DD];
__device__ float g_hbuf[NN*DD];
__device__ float g_t1  [NN*DD];
__device__ float g_t2  [NN*DD];
__device__ float g_q   [NN*DD];
__device__ float g_k   [NN*DD];
__device__ float g_v   [NN*DD];
__device__ float g_eaA [EE*DD];
__device__ float g_eaB [EE*DD];
__device__ float g_atoms [AA*DD];
__device__ float g_atoms2[AA*DD];
__device__ float g_a1  [AA*DD];
__device__ float g_a2  [AA*DD];
__device__ float g_logit[EE*HH];
__device__ unsigned g_m[NN*HH];
__device__ float g_den [NN*HH];
__device__ float g_results[AA];
__device__ float g_gstat[5*GG];

// ---------------- bf16 hi/lo mirrors ----------------
__device__ __nv_bfloat16 g_wth[50*16384];
__device__ __nv_bfloat16 g_wtl[50*16384];
__device__ __nv_bfloat16 g_curh[NN*DD],  g_curl[NN*DD];
__device__ __nv_bfloat16 g_hbh [NN*DD],  g_hbl [NN*DD];
__device__ __nv_bfloat16 g_t1h [NN*DD],  g_t1l [NN*DD];
__device__ __nv_bfloat16 g_t2h [NN*DD],  g_t2l [NN*DD];
__device__ __nv_bfloat16 g_qh  [NN*DD],  g_ql  [NN*DD];
__device__ __nv_bfloat16 g_eaAh[EE*DD],  g_eaAl[EE*DD];
__device__ __nv_bfloat16 g_eaBh[EE*DD],  g_eaBl[EE*DD];
__device__ __nv_bfloat16 g_sbh [EE*128], g_sbl [EE*128];
__device__ __nv_bfloat16 g_ath [AA*DD],  g_atl [AA*DD];
__device__ __nv_bfloat16 g_at2h[AA*DD],  g_at2l[AA*DD];
__device__ __nv_bfloat16 g_a1h [AA*DD],  g_a1l [AA*DD];

// ---------------- helpers ----------------
__device__ __forceinline__ float siluf(float v){ return v * (1.f / (1.f + __expf(-v))); }
__device__ __forceinline__ unsigned f2o(float f){ unsigned u=__float_as_uint(f); return (u&0x80000000u)? ~u : (u|0x80000000u); }
__device__ __forceinline__ float o2f(unsigned u){ return (u&0x80000000u)? __uint_as_float(u^0x80000000u) : __uint_as_float(~u); }
__device__ __forceinline__ void split_bf16(float v, __nv_bfloat16& h, __nv_bfloat16& l){
    h = __float2bfloat16(v);
    l = __float2bfloat16(v - __bfloat162float(h));
}
__device__ __forceinline__ uint32_t smem_u32(const void* p){
    uint32_t a;
    asm("{ .reg .u64 t; cvta.to.shared.u64 t, %1; cvt.u32.u64 %0, t; }" : "=r"(a) : "l"(p));
    return a;
}
__device__ __forceinline__ void ldm4(uint32_t* r, uint32_t addr){
    asm volatile("ldmatrix.sync.aligned.m8n8.x4.shared.b16 {%0,%1,%2,%3}, [%4];"
        : "=r"(r[0]),"=r"(r[1]),"=r"(r[2]),"=r"(r[3]) : "r"(addr));
}
__device__ __forceinline__ void mma16816(float* c, const uint32_t* a, const uint32_t* b){
    asm volatile("mma.sync.aligned.m16n8k16.row.col.f32.bf16.bf16.f32 "
        "{%0,%1,%2,%3}, {%4,%5,%6,%7}, {%8,%9}, {%0,%1,%2,%3};"
        : "+f"(c[0]),"+f"(c[1]),"+f"(c[2]),"+f"(c[3])
        : "r"(a[0]),"r"(a[1]),"r"(a[2]),"r"(a[3]), "r"(b[0]),"r"(b[1]));
}
// swizzled smem byte offset for 128x128 bf16 tile: row*256B, 16B chunks XOR'd by row&7
__device__ __forceinline__ uint32_t swz(int r, int k){
    return (uint32_t)((r<<8) + ((((k>>3) ^ (r&7)) & 15)<<4) + ((k&7)<<1));
}

#define OFF_AHI 0
#define OFF_ALO 32768
#define OFF_WHI 65536
#define OFF_WLO 98304
static constexpr int SMEM_T = 131072;

// ---------------- bf16 split tensor-core GEMM, pre-converted inputs ----------------
// C[M,128] = epi(A'[M,128]@W + bias);  A' gathered if GATHER. W is [n][k] bf16 hi/lo.
template<int ACT, bool GATHER, bool HASRES, bool WRITEC, bool EMIT>
__global__ __launch_bounds__(256)
void gemm_bf(const __nv_bfloat16* __restrict__ Ahi, const __nv_bfloat16* __restrict__ Alo,
             const __nv_bfloat16* __restrict__ Whi, const __nv_bfloat16* __restrict__ Wlo,
             const float* __restrict__ bias, const float* __restrict__ res,
             const int* __restrict__ gidx, float* __restrict__ C,
             __nv_bfloat16* __restrict__ Chi, __nv_bfloat16* __restrict__ Clo, int M)
{
    extern __shared__ __align__(128) char smem[];
    const int tid = threadIdx.x;
    const int lane = tid & 31, w = tid >> 5;
    const int row0 = blockIdx.x * 128;
    const int r8 = tid >> 4;        // 0..15
    const int ch = tid & 15;        // 16B chunk

    // ---- W load (pure LDG.128 -> STS.128) ----
    #pragma unroll
    for (int sw = 0; sw < 8; sw++){
        int n = sw*16 + r8;
        uint32_t so = swz(n, ch*8);
        *(uint4*)(smem + OFF_WHI + so) = *(const uint4*)(Whi + n*128 + ch*8);
        *(uint4*)(smem + OFF_WLO + so) = *(const uint4*)(Wlo + n*128 + ch*8);
    }
    // ---- A tile load ----
    #pragma unroll
    for (int sw = 0; sw < 8; sw++){
        int r = sw*16 + r8;
        int gr = row0 + r;
        uint4 vh = make_uint4(0,0,0,0), vl = make_uint4(0,0,0,0);
        if (gr < M){
            size_t ar = GATHER ? (size_t)__ldg(gidx + gr) : (size_t)gr;
            vh = *(const uint4*)(Ahi + ar*128 + ch*8);
            vl = *(const uint4*)(Alo + ar*128 + ch*8);
        }
        uint32_t so = swz(r, ch*8);
        *(uint4*)(smem + OFF_AHI + so) = vh;
        *(uint4*)(smem + OFF_ALO + so) = vl;
    }
    __syncthreads();

    const int m_warp = (w >> 2) * 64;   // 0 / 64
    const int n_warp = (w & 3) * 32;    // 0,32,64,96
    const uint32_t sb = smem_u32(smem);

    const int a_r = lane & 15;
    const int a_k = (lane >> 4) << 3;
    const int b_n = (lane & 7) + ((lane & 16) ? 8 : 0);
    const int b_k = lane & 8;

    float c[64];
    #pragma unroll
    for (int i = 0; i < 64; i++) c[i] = 0.f;

    #pragma unroll
    for (int ks = 0; ks < 8; ks++){
        const int k0 = ks * 16;
        uint32_t bh[8], bl[8];
        #pragma unroll
        for (int g = 0; g < 2; g++){
            uint32_t off = swz(n_warp + g*16 + b_n, k0 + b_k);
            ldm4(&bh[g*4], sb + OFF_WHI + off);
            ldm4(&bl[g*4], sb + OFF_WLO + off);
        }
        uint32_t ah[16], al[16];
        #pragma unroll
        for (int mt = 0; mt < 4; mt++){
            uint32_t off = swz(m_warp + mt*16 + a_r, k0 + a_k);
            ldm4(&ah[mt*4], sb + OFF_AHI + off);
            ldm4(&al[mt*4], sb + OFF_ALO + off);
        }
        #pragma unroll
        for (int mt = 0; mt < 4; mt++){
            #pragma unroll
            for (int nt = 0; nt < 4; nt++){
                float* cp = &c[(mt*4 + nt)*4];
                mma16816(cp, &ah[mt*4], &bh[nt*2]);
                mma16816(cp, &ah[mt*4], &bl[nt*2]);
                mma16816(cp, &al[mt*4], &bh[nt*2]);
            }
        }
    }

    // ---- epilogue from fragments ----
    #pragma unroll
    for (int mt = 0; mt < 4; mt++){
        #pragma unroll
        for (int nt = 0; nt < 4; nt++){
            const float* cp = &c[(mt*4 + nt)*4];
            int cb = n_warp + nt*8 + 2*(lane & 3);
            float2 bb = make_float2(0.f, 0.f);
            if (bias) bb = *reinterpret_cast<const float2*>(bias + cb);
            #pragma unroll
            for (int hh = 0; hh < 2; hh++){
                int gr = row0 + m_warp + mt*16 + (lane >> 2) + hh*8;
                if (gr >= M) continue;
                float v0 = cp[hh*2+0] + bb.x;
                float v1 = cp[hh*2+1] + bb.y;
                if (ACT==1){ v0 = siluf(v0); v1 = siluf(v1); }
                if (HASRES){
                    float2 rr = *reinterpret_cast<const float2*>(res + (size_t)gr*128 + cb);
                    v0 += rr.x; v1 += rr.y;
                }
                if (WRITEC)
                    *reinterpret_cast<float2*>(C + (size_t)gr*128 + cb) = make_float2(v0, v1);
                if (EMIT){
                    __nv_bfloat16 h0,l0,h1,l1;
                    split_bf16(v0,h0,l0); split_bf16(v1,h1,l1);
                    __nv_bfloat162 ph; ph.x=h0; ph.y=h1;
                    __nv_bfloat162 pl; pl.x=l0; pl.y=l1;
                    *reinterpret_cast<__nv_bfloat162*>(Chi + (size_t)gr*128 + cb) = ph;
                    *reinterpret_cast<__nv_bfloat162*>(Clo + (size_t)gr*128 + cb) = pl;
                }
            }
        }
    }
}

// ---------------- weight convert: fp32 [l][Kin][128] -> bf16 hi/lo [l][n][128k] (transposed, k-padded) ----------------
__global__ void conv_w_kernel(const float* __restrict__ W, __nv_bfloat16* __restrict__ Wh,
                              __nv_bfloat16* __restrict__ Wl, int nmat, int Kin)
{
    int idx = blockIdx.x*blockDim.x + threadIdx.x;
    if (idx >= nmat*16384) return;
    int l = idx >> 14;
    int n = (idx >> 7) & 127;
    int k = idx & 127;
    float v = (k < Kin) ? __ldg(W + ((size_t)l*Kin + k)*128 + n) : 0.f;
    __nv_bfloat16 h, lo; split_bf16(v, h, lo);
    Wh[idx] = h; Wl[idx] = lo;
}

// ---------------- activation convert: fp32 [M][Kin] -> bf16 hi/lo [M][128] (k-padded) ----------------
__global__ void conv_a_kernel(const float* __restrict__ A, __nv_bfloat16* __restrict__ Ah,
                              __nv_bfloat16* __restrict__ Al, int M, int Kin)
{
    int idx = blockIdx.x*blockDim.x + threadIdx.x;
    if (idx >= M*128) return;
    int r = idx >> 7, k = idx & 127;
    float v = (k < Kin) ? __ldg(A + (size_t)r*Kin + k) : 0.f;
    __nv_bfloat16 h, l; split_bf16(v, h, l);
    Ah[idx] = h; Al[idx] = l;
}

// ---------------- scatter rows: dst[idx[n],:] += src[n,:] ----------------
__global__ void scatter_rows_kernel(const float* __restrict__ src, const int* __restrict__ idx,
                                    float* __restrict__ dstb, int nrows)
{
    int i = blockIdx.x*blockDim.x + threadIdx.x;
    if (i >= nrows*32) return;
    int n = i >> 5, c4 = i & 31;
    int a = __ldg(idx + n);
    float4 v = *reinterpret_cast<const float4*>(src + (size_t)n*128 + c4*4);
    float* d = dstb + (size_t)a*128 + c4*4;
    atomicAdd(d+0,v.x); atomicAdd(d+1,v.y); atomicAdd(d+2,v.z); atomicAdd(d+3,v.w);
}

// ---------------- rbf gate ----------------
__global__ void gate_mul_kernel(float* __restrict__ h, const float* __restrict__ rbf,
                                const float* __restrict__ W)
{
    __shared__ float Ws[RBFD][DD];
    for (int t=threadIdx.x; t<RBFD*DD; t+=256) ((float*)Ws)[t] = W[t];
    __syncthreads();
    int c   = threadIdx.x & 127;
    int sub = threadIdx.x >> 7;
    int n0  = blockIdx.x*128;
    int nend = min(n0+128, NN);
    for (int n = n0+sub; n < nend; n += 2){
        const float* r = rbf + (size_t)n*RBFD;
        float g = 0.f;
        #pragma unroll
        for (int kk=0;kk<RBFD;kk++) g = fmaf(__ldg(r+kk), Ws[kk][c], g);
        h[(size_t)n*DD+c] *= g;
    }
}

// ---------------- readout gate + scatter ----------------
__global__ void gate_scatter_kernel(const float* __restrict__ h, const float* __restrict__ rbf,
                                    const float* __restrict__ W, const int* __restrict__ idx,
                                    float* __restrict__ atoms)
{
    __shared__ float Ws[RBFD][DD];
    for (int t=threadIdx.x; t<RBFD*DD; t+=256) ((float*)Ws)[t] = W[t];
    __syncthreads();
    int c   = threadIdx.x & 127;
    int sub = threadIdx.x >> 7;
    int n0  = blockIdx.x*128;
    int nend = min(n0+128, NN);
    for (int n = n0+sub; n < nend; n += 2){
        const float* r = rbf + (size_t)n*RBFD;
        float g = 0.f;
        #pragma unroll
        for (int kk=0;kk<RBFD;kk++) g = fmaf(__ldg(r+kk), Ws[kk][c], g);
        atomicAdd(&atoms[(size_t)__ldg(idx+n)*DD + c], h[(size_t)n*DD+c]*g);
    }
}

// ---------------- attention ----------------
__global__ void logit_kernel(const float* __restrict__ q, const float* __restrict__ k,
                             const float* __restrict__ ek, const int* __restrict__ src,
                             const int* __restrict__ dst, float* __restrict__ logit,
                             unsigned* __restrict__ mOrd)
{
    int i = blockIdx.x*blockDim.x + threadIdx.x;
    if (i >= EE*HH) return;
    int e = i >> 3, h = i & 7;
    int s = __ldg(src+e), d = __ldg(dst+e);
    const float4* qp = (const float4*)(q  + (size_t)d*DD + h*CC);
    const float4* kp = (const float4*)(k  + (size_t)s*DD + h*CC);
    const float4* ep = (const float4*)(ek + (size_t)e*DD + h*CC);
    float acc = 0.f;
    #pragma unroll
    for (int j=0;j<4;j++){
        float4 a=qp[j], b=kp[j], c=ep[j];
        acc += a.x*(b.x+c.x)+a.y*(b.y+c.y)+a.z*(b.z+c.z)+a.w*(b.w+c.w);
    }
    acc *= 0.25f;
    logit[i] = acc;
    atomicMax(&mOrd[(size_t)d*HH+h], f2o(acc));
}

__global__ void exp_kernel(const int* __restrict__ dst, float* __restrict__ logit,
                           const unsigned* __restrict__ mOrd, float* __restrict__ den)
{
    int i = blockIdx.x*blockDim.x + threadIdx.x;
    if (i >= EE*HH) return;
    int e = i >> 3, h = i & 7;
    int d = __ldg(dst+e);
    float m  = o2f(mOrd[(size_t)d*HH+h]);
    float ex = __expf(logit[i] - m);
    logit[i] = ex;
    atomicAdd(&den[(size_t)d*HH+h], ex);
}

__global__ void msg_kernel(const float* __restrict__ v, const float* __restrict__ ek,
                           const float* __restrict__ sw, const float* __restrict__ ex,
                           const float* __restrict__ den, const int* __restrict__ src,
                           const int* __restrict__ dst, float* __restrict__ hout)
{
    int i = blockIdx.x*blockDim.x + threadIdx.x;
    if (i >= EE*32) return;
    int e = i >> 5, c4 = i & 31, h = c4 >> 2;
    int sN = __ldg(src+e), dN = __ldg(dst+e);
    float alpha = __ldg(ex + (size_t)e*HH + h) / (__ldg(den + (size_t)dN*HH + h) + 1e-16f);
    float4 vv = *(const float4*)(v  + (size_t)sN*DD + c4*4);
    float4 ee = *(const float4*)(ek + (size_t)e*DD  + c4*4);
    float4 ww = *(const float4*)(sw + (size_t)e*DD  + c4*4);
    float* o = hout + (size_t)dN*DD + c4*4;
    atomicAdd(o+0, (vv.x+ee.x)*alpha*ww.x);
    atomicAdd(o+1, (vv.y+ee.y)*alpha*ww.y);
    atomicAdd(o+2, (vv.z+ee.z)*alpha*ww.z);
    atomicAdd(o+3, (vv.w+ee.w)*alpha*ww.w);
}

// ---------------- graph norm ----------------
__global__ void gn_pass1_kernel(const float* __restrict__ h, const int* __restrict__ batch,
                                float* __restrict__ gstat)
{
    int gi = blockIdx.x*blockDim.x + threadIdx.x;
    int n = gi >> 5, lane = gi & 31;
    if (n >= NN) return;
    float4 v = *reinterpret_cast<const float4*>(h + (size_t)n*128 + lane*4);
    float s = v.x+v.y+v.z+v.w;
    #pragma unroll
    for(int o=16;o;o>>=1) s += __shfl_xor_sync(0xffffffffu, s, o);
    if (!lane){
        int g = __ldg(batch+n);
        atomicAdd(&gstat[g], s);
        atomicAdd(&gstat[GG+g], 1.f);
    }
}
__global__ void gn_mean_kernel(float* gstat)
{
    int g = threadIdx.x;
    if (g >= GG) return;
    float cnt = gstat[GG+g]*128.f;
    gstat[2*GG+g] = (cnt > 0.f) ? gstat[g]/cnt : 0.f;
}
__global__ void gn_pass2_kernel(const float* __restrict__ h, const int* __restrict__ batch,
                                float* __restrict__ gstat)
{
    int gi = blockIdx.x*blockDim.x + threadIdx.x;
    int n = gi >> 5, lane = gi & 31;
    if (n >= NN) return;
    int g = __ldg(batch+n);
    float mean = gstat[2*GG+g];
    float4 v = *reinterpret_cast<const float4*>(h + (size_t)n*128 + lane*4);
    float a=v.x-mean, b=v.y-mean, c=v.z-mean, d=v.w-mean;
    float s = a*a+b*b+c*c+d*d;
    #pragma unroll
    for(int o=16;o;o>>=1) s += __shfl_xor_sync(0xffffffffu, s, o);
    if (!lane) atomicAdd(&gstat[3*GG+g], s);
}
__global__ void gn_rstd_kernel(float* gstat)
{
    int g = threadIdx.x;
    if (g >= GG) return;
    float cnt = gstat[GG+g]*128.f;
    float var = (cnt > 0.f) ? gstat[3*GG+g]/cnt : 0.f;
    gstat[4*GG+g] = rsqrtf(var + 1e-8f);
}
// gn apply + bf16 hi/lo emission (feeds bf1 GEMM)
__global__ void gn_apply_kernel(float* __restrict__ h, const int* __restrict__ batch,
                                const float* __restrict__ gstat,
                                __nv_bfloat16* __restrict__ Hh, __nv_bfloat16* __restrict__ Hl)
{
    int i = blockIdx.x*blockDim.x + threadIdx.x;
    if (i >= NN*32) return;
    int n = i >> 5;
    int g = __ldg(batch+n);
    float mean = gstat[2*GG+g], rstd = gstat[4*GG+g];
    size_t base = (size_t)n*128 + (i&31)*4;
    float4 v = *reinterpret_cast<const float4*>(h + base);
    v.x=(v.x-mean)*rstd; v.y=(v.y-mean)*rstd; v.z=(v.z-mean)*rstd; v.w=(v.w-mean)*rstd;
    *reinterpret_cast<float4*>(h + base) = v;
    __nv_bfloat16 h0,l0,h1,l1,h2,l2,h3,l3;
    split_bf16(v.x,h0,l0); split_bf16(v.y,h1,l1);
    split_bf16(v.z,h2,l2); split_bf16(v.w,h3,l3);
    __nv_bfloat162 p0; p0.x=h0; p0.y=h1;
    __nv_bfloat162 p1; p1.x=h2; p1.y=h3;
    __nv_bfloat162 q0; q0.x=l0; q0.y=l1;
    __nv_bfloat162 q1; q1.x=l2; q1.y=l3;
    *reinterpret_cast<__nv_bfloat162*>(Hh + base)     = p0;
    *reinterpret_cast<__nv_bfloat162*>(Hh + base + 2) = p1;
    *reinterpret_cast<__nv_bfloat162*>(Hl + base)     = q0;
    *reinterpret_cast<__nv_bfloat162*>(Hl + base + 2) = q1;
}

// ---------------- readout final dot ----------------
__global__ void readout_dot_kernel(const float* __restrict__ a2, const float* __restrict__ w3,
                                   const float* __restrict__ b3, float* __restrict__ results)
{
    int gi = blockIdx.x*blockDim.x + threadIdx.x;
    int a = gi >> 5, lane = gi & 31;
    if (a >= AA) return;
    float4 x = *(const float4*)(a2 + (size_t)a*128 + lane*4);
    float4 w = *(const float4*)(w3 + lane*4);
    float s = x.x*w.x + x.y*w.y + x.z*w.z + x.w*w.w;
    #pragma unroll
    for(int o=16;o;o>>=1) s += __shfl_xor_sync(0xffffffffu, s, o);
    if (!lane) results[a] += s + __ldg(b3);
}

// ---------------- final ----------------
__global__ void final_kernel(const float* __restrict__ results, const int* __restrict__ atom_batch,
                             float* __restrict__ out)
{
    int a = blockIdx.x*blockDim.x + threadIdx.x;
    if (a < AA) atomicAdd(&out[__ldg(atom_batch+a)], results[a]*(1.f/3.f));
}

// =======================================================================
extern "C" void kernel_launch(void* const* d_in, const int* in_sizes, int n_in,
                              void* d_out, int out_size)
{
    cudaStream_t s = 0;
    const float* x            = (const float*)d_in[0];
    const float* node_rbf     = (const float*)d_in[1];
    const float* edge_sbf     = (const float*)d_in[2];
    const int*   edge_index   = (const int*)  d_in[3];
    const int*   srcp = edge_index;
    const int*   dstp = edge_index + EE;
    const int*   pair_atom_idx= (const int*)  d_in[4];
    const int*   edge_index_0 = (const int*)  d_in[5];
    const int*   atom_batch   = (const int*)  d_in[6];
    const int*   batch        = (const int*)  d_in[7];
    const float* edgenn_w1    = (const float*)d_in[8];
    const float* edgenn_b1    = (const float*)d_in[9];
    const float* edgenn_w2    = (const float*)d_in[10];
    const float* edgenn_b2    = (const float*)d_in[11];
    const float* conv_wq      = (const float*)d_in[12];
    const float* conv_wk      = (const float*)d_in[13];
    const float* conv_wv      = (const float*)d_in[14];
    const float* conv_we      = (const float*)d_in[15];
    const float* conv_wsbf    = (const float*)d_in[16];
    const float* conv_bsbf    = (const float*)d_in[17];
    const float* conv_wrbf    = (const float*)d_in[18];
    const float* dense_w      = (const float*)d_in[19];
    const float* dense_b      = (const float*)d_in[20];
    const float* bf_w         = (const float*)d_in[21];
    const float* bf_b         = (const float*)d_in[22];
    const float* af_w         = (const float*)d_in[23];
    const float* af_b         = (const float*)d_in[24];
    const float* read_wrbf    = (const float*)d_in[25];
    const float* read_w1      = (const float*)d_in[26];
    const float* read_b1      = (const float*)d_in[27];
    const float* read_w2      = (const float*)d_in[28];
    const float* read_b2      = (const float*)d_in[29];
    const float* read_w3      = (const float*)d_in[30];
    const float* read_b3      = (const float*)d_in[31];

    cudaFuncSetAttribute((void*)gemm_bf<1,true ,false,false,true >, cudaFuncAttributeMaxDynamicSharedMemorySize, SMEM_T);
    cudaFuncSetAttribute((void*)gemm_bf<0,false,false,false,true >, cudaFuncAttributeMaxDynamicSharedMemorySize, SMEM_T);
    cudaFuncSetAttribute((void*)gemm_bf<0,false,false,true ,false>, cudaFuncAttributeMaxDynamicSharedMemorySize, SMEM_T);
    cudaFuncSetAttribute((void*)gemm_bf<1,false,false,false,true >, cudaFuncAttributeMaxDynamicSharedMemorySize, SMEM_T);
    cudaFuncSetAttribute((void*)gemm_bf<1,false,true ,false,true >, cudaFuncAttributeMaxDynamicSharedMemorySize, SMEM_T);
    cudaFuncSetAttribute((void*)gemm_bf<1,false,true ,true ,true >, cudaFuncAttributeMaxDynamicSharedMemorySize, SMEM_T);
    cudaFuncSetAttribute((void*)gemm_bf<1,false,false,true ,false>, cudaFuncAttributeMaxDynamicSharedMemorySize, SMEM_T);

    float *cur_w, *hbuf, *t1, *t2, *q, *k_, *v_, *eaA, *eaB;
    float *atoms, *atoms2, *a1, *a2, *logit, *den, *results, *gstat;
    unsigned* mOrd;
    __nv_bfloat16 *wth, *wtl, *curh, *curl, *hbh, *hbl, *t1h, *t1l, *t2h, *t2l;
    __nv_bfloat16 *qh, *ql, *eaAh, *eaAl, *eaBh, *eaBl, *sbh, *sbl;
    __nv_bfloat16 *ath, *atl, *at2h, *at2l, *a1h, *a1l;
    cudaGetSymbolAddress((void**)&cur_w,  g_cur);
    cudaGetSymbolAddress((void**)&hbuf,   g_hbuf);
    cudaGetSymbolAddress((void**)&t1,     g_t1);
    cudaGetSymbolAddress((void**)&t2,     g_t2);
    cudaGetSymbolAddress((void**)&q,      g_q);
    cudaGetSymbolAddress((void**)&k_,     g_k);
    cudaGetSymbolAddress((void**)&v_,     g_v);
    cudaGetSymbolAddress((void**)&eaA,    g_eaA);
    cudaGetSymbolAddress((void**)&eaB,    g_eaB);
    cudaGetSymbolAddress((void**)&atoms,  g_atoms);
    cudaGetSymbolAddress((void**)&atoms2, g_atoms2);
    cudaGetSymbolAddress((void**)&a1,     g_a1);
    cudaGetSymbolAddress((void**)&a2,     g_a2);
    cudaGetSymbolAddress((void**)&logit,  g_logit);
    cudaGetSymbolAddress((void**)&mOrd,   g_m);
    cudaGetSymbolAddress((void**)&den,    g_den);
    cudaGetSymbolAddress((void**)&results,g_results);
    cudaGetSymbolAddress((void**)&gstat,  g_gstat);
    cudaGetSymbolAddress((void**)&wth,  g_wth);   cudaGetSymbolAddress((void**)&wtl,  g_wtl);
    cudaGetSymbolAddress((void**)&curh, g_curh);  cudaGetSymbolAddress((void**)&curl, g_curl);
    cudaGetSymbolAddress((void**)&hbh,  g_hbh);   cudaGetSymbolAddress((void**)&hbl,  g_hbl);
    cudaGetSymbolAddress((void**)&t1h,  g_t1h);   cudaGetSymbolAddress((void**)&t1l,  g_t1l);
    cudaGetSymbolAddress((void**)&t2h,  g_t2h);   cudaGetSymbolAddress((void**)&t2l,  g_t2l);
    cudaGetSymbolAddress((void**)&qh,   g_qh);    cudaGetSymbolAddress((void**)&ql,   g_ql);
    cudaGetSymbolAddress((void**)&eaAh, g_eaAh);  cudaGetSymbolAddress((void**)&eaAl, g_eaAl);
    cudaGetSymbolAddress((void**)&eaBh, g_eaBh);  cudaGetSymbolAddress((void**)&eaBl, g_eaBl);
    cudaGetSymbolAddress((void**)&sbh,  g_sbh);   cudaGetSymbolAddress((void**)&sbl,  g_sbl);
    cudaGetSymbolAddress((void**)&ath,  g_ath);   cudaGetSymbolAddress((void**)&atl,  g_atl);
    cudaGetSymbolAddress((void**)&at2h, g_at2h);  cudaGetSymbolAddress((void**)&at2l, g_at2l);
    cudaGetSymbolAddress((void**)&a1h,  g_a1h);   cudaGetSymbolAddress((void**)&a1l,  g_a1l);

    auto WTH = [&](int slot){ return wth + (size_t)slot*16384; };
    auto WTL = [&](int slot){ return wtl + (size_t)slot*16384; };

    // ---- one-time weight conversion (slots) ----
    auto convw = [&](const float* W, int slot, int nmat, int Kin){
        conv_w_kernel<<<(nmat*16384+255)/256, 256, 0, s>>>(W, WTH(slot), WTL(slot), nmat, Kin);
    };
    convw(edgenn_w1, 0, 3, 128);
    convw(edgenn_w2, 3, 3, 128);
    convw(conv_wq,   6, 3, 128);
    convw(conv_wk,   9, 3, 128);
    convw(conv_wv,  12, 3, 128);
    convw(conv_we,  15, 3, 128);
    convw(conv_wsbf,18, 3, 112);
    convw(dense_w,  21, 3, 128);
    convw(bf_w,     24, 6, 128);
    convw(af_w,     30,12, 128);
    convw(read_w1,  42, 4, 128);
    convw(read_w2,  46, 4, 128);
    // one-time activation converts
    conv_a_kernel<<<(NN*128+255)/256, 256, 0, s>>>(x, curh, curl, NN, 128);
    conv_a_kernel<<<(EE*128+255)/256, 256, 0, s>>>(edge_sbf, sbh, sbl, EE, 112);

    auto readout = [&](int i, const float* h){
        cudaMemsetAsync(atoms2, 0, (size_t)AA*DD*4, s);
        gate_scatter_kernel<<<(NN+127)/128, 256, 0, s>>>(
            h, node_rbf, read_wrbf + (size_t)i*RBFD*DD, edge_index_0, atoms2);
        conv_a_kernel<<<(AA*128+255)/256, 256, 0, s>>>(atoms2, at2h, at2l, AA, 128);
        gemm_bf<1,false,false,false,true><<<(AA+127)/128,256,SMEM_T,s>>>(
            at2h, at2l, WTH(42+i), WTL(42+i), read_b1 + (size_t)i*DD,
            nullptr, nullptr, nullptr, a1h, a1l, AA);
        gemm_bf<1,false,false,true,false><<<(AA+127)/128,256,SMEM_T,s>>>(
            a1h, a1l, WTH(46+i), WTL(46+i), read_b2 + (size_t)i*DD,
            nullptr, nullptr, a2, nullptr, nullptr, AA);
        readout_dot_kernel<<<(AA*32+255)/256, 256, 0, s>>>(
            a2, read_w3 + (size_t)i*DD, read_b3 + i, results);
    };

    // ---- init ----
    cudaMemsetAsync(results, 0, (size_t)AA*4, s);
    readout(0, x);
    const float* cur = x;
    const int GN = (NN+127)/128, GE = (EE+127)/128;

    for (int i = 0; i < LLAYERS; i++){
        // atoms_rep = segsum(cur, edge_index_0)
        cudaMemsetAsync(atoms, 0, (size_t)AA*DD*4, s);
        scatter_rows_kernel<<<(NN*32+255)/256, 256, 0, s>>>(cur, edge_index_0, atoms, NN);
        conv_a_kernel<<<(AA*128+255)/256, 256, 0, s>>>(atoms, ath, atl, AA, 128);
        // edgenn: ea = silu(atoms[pair]@w1+b1)@w2+b2  (pair-resident, emit only)
        gemm_bf<1,true,false,false,true><<<GE,256,SMEM_T,s>>>(
            ath, atl, WTH(0+i), WTL(0+i), edgenn_b1 + (size_t)i*DD,
            nullptr, pair_atom_idx, nullptr, eaAh, eaAl, EE);
        gemm_bf<0,false,false,false,true><<<GE,256,SMEM_T,s>>>(
            eaAh, eaAl, WTH(3+i), WTL(3+i), edgenn_b2 + (size_t)i*DD,
            nullptr, nullptr, nullptr, eaBh, eaBl, EE);
        // q,k,v (fp32 out)
        gemm_bf<0,false,false,true,false><<<GN,256,SMEM_T,s>>>(
            curh, curl, WTH(6+i), WTL(6+i), nullptr, nullptr, nullptr, q, nullptr, nullptr, NN);
        gemm_bf<0,false,false,true,false><<<GN,256,SMEM_T,s>>>(
            curh, curl, WTH(9+i), WTL(9+i), nullptr, nullptr, nullptr, k_, nullptr, nullptr, NN);
        gemm_bf<0,false,false,true,false><<<GN,256,SMEM_T,s>>>(
            curh, curl, WTH(12+i), WTL(12+i), nullptr, nullptr, nullptr, v_, nullptr, nullptr, NN);
        // ek = ea @ we (fp32 out)
        gemm_bf<0,false,false,true,false><<<GE,256,SMEM_T,s>>>(
            eaBh, eaBl, WTH(15+i), WTL(15+i), nullptr, nullptr, nullptr, eaA, nullptr, nullptr, EE);
        // sw = sbf @ wsbf + bsbf (fp32 out)
        gemm_bf<0,false,false,true,false><<<GE,256,SMEM_T,s>>>(
            sbh, sbl, WTH(18+i), WTL(18+i), conv_bsbf + (size_t)i*DD,
            nullptr, nullptr, eaB, nullptr, nullptr, EE);
        // attention softmax over dst
        cudaMemsetAsync(mOrd, 0, (size_t)NN*HH*4, s);
        cudaMemsetAsync(den,  0, (size_t)NN*HH*4, s);
        logit_kernel<<<(EE*HH+255)/256, 256, 0, s>>>(q, k_, eaA, srcp, dstp, logit, mOrd);
        exp_kernel  <<<(EE*HH+255)/256, 256, 0, s>>>(dstp, logit, mOrd, den);
        cudaMemsetAsync(hbuf, 0, (size_t)NN*DD*4, s);
        msg_kernel  <<<(EE*32+255)/256, 256, 0, s>>>(v_, eaA, eaB, logit, den, srcp, dstp, hbuf);
        // rbf gate + graph norm (gn_apply emits hbuf pair)
        gate_mul_kernel<<<GN, 256, 0, s>>>(hbuf, node_rbf, conv_wrbf + (size_t)i*RBFD*DD);
        cudaMemsetAsync(gstat, 0, 5*GG*4, s);
        gn_pass1_kernel<<<(NN*32+255)/256, 256, 0, s>>>(hbuf, batch, gstat);
        gn_mean_kernel <<<1, GG, 0, s>>>(gstat);
        gn_pass2_kernel<<<(NN*32+255)/256, 256, 0, s>>>(hbuf, batch, gstat);
        gn_rstd_kernel <<<1, GG, 0, s>>>(gstat);
        gn_apply_kernel<<<(NN*32+255)/256, 256, 0, s>>>(hbuf, batch, gstat, hbh, hbl);
        // bf residual block
        gemm_bf<1,false,false,false,true><<<GN,256,SMEM_T,s>>>(
            hbh, hbl, WTH(24+i*2), WTL(24+i*2), bf_b + (size_t)i*2*DD,
            nullptr, nullptr, nullptr, t1h, t1l, NN);
        gemm_bf<1,false,true,false,true><<<GN,256,SMEM_T,s>>>(
            t1h, t1l, WTH(24+i*2+1), WTL(24+i*2+1), bf_b + (size_t)i*2*DD + DD,
            hbuf, nullptr, nullptr, t2h, t2l, NN);
        // dense + residual(cur) -> t1 fp32 + pair
        gemm_bf<1,false,true,true,true><<<GN,256,SMEM_T,s>>>(
            t2h, t2l, WTH(21+i), WTL(21+i), dense_b + (size_t)i*DD,
            cur, nullptr, t1, t1h, t1l, NN);
        // af block 1
        gemm_bf<1,false,false,false,true><<<GN,256,SMEM_T,s>>>(
            t1h, t1l, WTH(30+i*4), WTL(30+i*4), af_b + (size_t)i*4*DD,
            nullptr, nullptr, nullptr, qh, ql, NN);
        gemm_bf<1,false,true,true,true><<<GN,256,SMEM_T,s>>>(
            qh, ql, WTH(30+i*4+1), WTL(30+i*4+1), af_b + (size_t)i*4*DD + DD,
            t1, nullptr, t2, t2h, t2l, NN);
        // af block 2
        gemm_bf<1,false,false,false,true><<<GN,256,SMEM_T,s>>>(
            t2h, t2l, WTH(30+i*4+2), WTL(30+i*4+2), af_b + (size_t)i*4*DD + 2*DD,
            nullptr, nullptr, nullptr, qh, ql, NN);
        gemm_bf<1,false,true,true,true><<<GN,256,SMEM_T,s>>>(
            qh, ql, WTH(30+i*4+3), WTL(30+i*4+3), af_b + (size_t)i*4*DD + 3*DD,
            t2, nullptr, cur_w, curh, curl, NN);
        cur = cur_w;
        readout(i+1, cur);
    }

    cudaMemsetAsync(d_out, 0, (size_t)GG*4, s);
    final_kernel<<<(AA+255)/256, 256, 0, s>>>(results, atom_batch, (float*)d_out);
}

// round 5
// speedup vs baseline: 1.4813x; 1.0606x over previous
#include <cuda_runtime.h>
#include <cuda_bf16.h>
#include <math.h>
#include <stdint.h>

#define NN 60000
#define EE 300000
#define AA 8000
#define GG 256
#define DD 128
#define HH 8
#define CC 16
#define RBFD 16
#define SBFD 112
#define LLAYERS 3

// ---------------- fp32 scratch ----------------
__device__ float g_cur [NN*DD];
__device__ float g_hbuf[NN*DD];
__device__ float g_t1  [NN*DD];
__device__ float g_t2  [NN*DD];
__device__ float g_q   [NN*DD];
__device__ float g_k   [NN*DD];
__device__ float g_v   [NN*DD];
__device__ float g_eaA [EE*DD];
__device__ float g_eaB [EE*DD];
__device__ float g_atoms [AA*DD];
__device__ float g_atoms2[AA*DD];
__device__ float g_a1  [AA*DD];
__device__ float g_a2  [AA*DD];
__device__ float g_logit[EE*HH];
__device__ unsigned g_m[NN*HH];
__device__ float g_den [NN*HH];
__device__ float g_results[AA];
__device__ float g_gstat[5*GG];

// ---------------- bf16 hi/lo mirrors ----------------
__device__ __nv_bfloat16 g_wth[50*16384];
__device__ __nv_bfloat16 g_wtl[50*16384];
__device__ __nv_bfloat16 g_curh[NN*DD],  g_curl[NN*DD];
__device__ __nv_bfloat16 g_hbh [NN*DD],  g_hbl [NN*DD];
__device__ __nv_bfloat16 g_t1h [NN*DD],  g_t1l [NN*DD];
__device__ __nv_bfloat16 g_t2h [NN*DD],  g_t2l [NN*DD];
__device__ __nv_bfloat16 g_qh  [NN*DD],  g_ql  [NN*DD];
__device__ __nv_bfloat16 g_eaAh[EE*DD],  g_eaAl[EE*DD];
__device__ __nv_bfloat16 g_eaBh[EE*DD],  g_eaBl[EE*DD];
__device__ __nv_bfloat16 g_sbh [EE*128], g_sbl [EE*128];
__device__ __nv_bfloat16 g_ath [AA*DD],  g_atl [AA*DD];
__device__ __nv_bfloat16 g_at2h[AA*DD],  g_at2l[AA*DD];
__device__ __nv_bfloat16 g_a1h [AA*DD],  g_a1l [AA*DD];

// ---------------- helpers ----------------
__device__ __forceinline__ float siluf(float v){ return v * (1.f / (1.f + __expf(-v))); }
__device__ __forceinline__ unsigned f2o(float f){ unsigned u=__float_as_uint(f); return (u&0x80000000u)? ~u : (u|0x80000000u); }
__device__ __forceinline__ float o2f(unsigned u){ return (u&0x80000000u)? __uint_as_float(u^0x80000000u) : __uint_as_float(~u); }
__device__ __forceinline__ void split_bf16(float v, __nv_bfloat16& h, __nv_bfloat16& l){
    h = __float2bfloat16(v);
    l = __float2bfloat16(v - __bfloat162float(h));
}
__device__ __forceinline__ uint32_t smem_u32(const void* p){
    uint32_t a;
    asm("{ .reg .u64 t; cvta.to.shared.u64 t, %1; cvt.u32.u64 %0, t; }" : "=r"(a) : "l"(p));
    return a;
}
__device__ __forceinline__ void ldm4(uint32_t* r, uint32_t addr){
    asm volatile("ldmatrix.sync.aligned.m8n8.x4.shared.b16 {%0,%1,%2,%3}, [%4];"
        : "=r"(r[0]),"=r"(r[1]),"=r"(r[2]),"=r"(r[3]) : "r"(addr));
}
__device__ __forceinline__ void mma16816(float* c, const uint32_t* a, const uint32_t* b){
    asm volatile("mma.sync.aligned.m16n8k16.row.col.f32.bf16.bf16.f32 "
        "{%0,%1,%2,%3}, {%4,%5,%6,%7}, {%8,%9}, {%0,%1,%2,%3};"
        : "+f"(c[0]),"+f"(c[1]),"+f"(c[2]),"+f"(c[3])
        : "r"(a[0]),"r"(a[1]),"r"(a[2]),"r"(a[3]), "r"(b[0]),"r"(b[1]));
}
__device__ __forceinline__ void cpasync16(uint32_t dst, const void* src, int srcsize){
    asm volatile("cp.async.cg.shared.global [%0], [%1], 16, %2;"
        :: "r"(dst), "l"(src), "r"(srcsize) : "memory");
}
#define CP_COMMIT() asm volatile("cp.async.commit_group;" ::: "memory")
#define CP_WAIT1()  asm volatile("cp.async.wait_group 1;" ::: "memory")

// swizzled smem byte offset for 128x128 bf16 tile: row*256B, 16B chunks XOR'd by row&7
__device__ __forceinline__ uint32_t swz(int r, int k){
    return (uint32_t)((r<<8) + ((((k>>3) ^ (r&7)) & 15)<<4) + ((k&7)<<1));
}

#define OFF_WHI 0
#define OFF_WLO 32768
#define OFF_S0  65536
#define OFF_S1  131072
static constexpr int SMEM_T = 196608;

// ---------------- persistent pipelined bf16-split tensor-core GEMM ----------------
// C[M,128] = epi(A'[M,128]@W + bias);  W resident in smem; A double-buffered via cp.async.
template<int ACT, bool GATHER, bool HASRES, bool WRITEC, bool EMIT>
__global__ __launch_bounds__(256)
void gemm_bf(const __nv_bfloat16* __restrict__ Ahi, const __nv_bfloat16* __restrict__ Alo,
             const __nv_bfloat16* __restrict__ Whi, const __nv_bfloat16* __restrict__ Wlo,
             const float* __restrict__ bias, const float* __restrict__ res,
             const int* __restrict__ gidx, float* __restrict__ C,
             __nv_bfloat16* __restrict__ Chi, __nv_bfloat16* __restrict__ Clo, int M)
{
    extern __shared__ __align__(128) char smem[];
    const int tid = threadIdx.x;
    const int lane = tid & 31, w = tid >> 5;
    const int r8 = tid >> 4;        // 0..15
    const int ch = tid & 15;        // 16B chunk within 256B row
    const int tiles = (M + 127) >> 7;
    const uint32_t sb = smem_u32(smem);

    // ---- W resident load (once) ----
    #pragma unroll
    for (int sw = 0; sw < 8; sw++){
        int n = sw*16 + r8;
        uint32_t so = swz(n, ch*8);
        *(uint4*)(smem + OFF_WHI + so) = *(const uint4*)(Whi + n*128 + ch*8);
        *(uint4*)(smem + OFF_WLO + so) = *(const uint4*)(Wlo + n*128 + ch*8);
    }

    auto loadA = [&](int t, int soff){
        int row0t = t * 128;
        #pragma unroll
        for (int sw = 0; sw < 8; sw++){
            int r = sw*16 + r8;
            int gr = row0t + r;
            int ok = (gr < M) ? 16 : 0;
            size_t ar = 0;
            if (gr < M) ar = GATHER ? (size_t)__ldg(gidx + gr) : (size_t)gr;
            uint32_t so = swz(r, ch*8);
            cpasync16(sb + soff + so,         Ahi + ar*128 + ch*8, ok);
            cpasync16(sb + soff + 32768 + so, Alo + ar*128 + ch*8, ok);
        }
    };

    if (blockIdx.x < (unsigned)tiles) loadA(blockIdx.x, OFF_S0);
    CP_COMMIT();
    __syncthreads();   // W visible

    const int m_warp = (w >> 2) * 64;
    const int n_warp = (w & 3) * 32;
    const int a_r = lane & 15;
    const int a_k = (lane >> 4) << 3;
    const int b_n = (lane & 7) + ((lane & 16) ? 8 : 0);
    const int b_k = lane & 8;

    // ---- B fragments from resident W (loaded once per CTA) ----
    uint32_t bh[4][8], bl[4][8];
    // defer until after first wait? W is plain-stored and sync'd; load now.
    #pragma unroll
    for (int ks = 0; ks < 8; ks++){
        // we re-load B frags per ks inside the loop below instead (register pressure);
        break;
    }

    int p = 0;
    for (int t = blockIdx.x; t < tiles; t += gridDim.x){
        int tn = t + gridDim.x;
        if (tn < tiles) loadA(tn, p ? OFF_S0 : OFF_S1);
        CP_COMMIT();
        CP_WAIT1();
        __syncthreads();

        const uint32_t soff = sb + (p ? OFF_S1 : OFF_S0);
        float c[64];
        #pragma unroll
        for (int i = 0; i < 64; i++) c[i] = 0.f;

        #pragma unroll
        for (int ks = 0; ks < 8; ks++){
            const int k0 = ks * 16;
            uint32_t Bh[8], Bl[8];
            #pragma unroll
            for (int g = 0; g < 2; g++){
                uint32_t off = swz(n_warp + g*16 + b_n, k0 + b_k);
                ldm4(&Bh[g*4], sb + OFF_WHI + off);
                ldm4(&Bl[g*4], sb + OFF_WLO + off);
            }
            uint32_t Ah[16], Al[16];
            #pragma unroll
            for (int mt = 0; mt < 4; mt++){
                uint32_t off = swz(m_warp + mt*16 + a_r, k0 + a_k);
                ldm4(&Ah[mt*4], soff + off);
                ldm4(&Al[mt*4], soff + 32768 + off);
            }
            #pragma unroll
            for (int mt = 0; mt < 4; mt++){
                #pragma unroll
                for (int nt = 0; nt < 4; nt++){
                    float* cp = &c[(mt*4 + nt)*4];
                    mma16816(cp, &Ah[mt*4], &Bh[nt*2]);
                    mma16816(cp, &Ah[mt*4], &Bl[nt*2]);
                    mma16816(cp, &Al[mt*4], &Bh[nt*2]);
                }
            }
        }
        __syncthreads();   // all reads of stage p done before it is overwritten next iter

        // ---- epilogue ----
        int row0 = t*128;
        #pragma unroll
        for (int mt = 0; mt < 4; mt++){
            #pragma unroll
            for (int nt = 0; nt < 4; nt++){
                const float* cp = &c[(mt*4 + nt)*4];
                int cb = n_warp + nt*8 + 2*(lane & 3);
                float2 bb = make_float2(0.f, 0.f);
                if (bias) bb = *reinterpret_cast<const float2*>(bias + cb);
                #pragma unroll
                for (int hh = 0; hh < 2; hh++){
                    int gr = row0 + m_warp + mt*16 + (lane >> 2) + hh*8;
                    if (gr >= M) continue;
                    float v0 = cp[hh*2+0] + bb.x;
                    float v1 = cp[hh*2+1] + bb.y;
                    if (ACT==1){ v0 = siluf(v0); v1 = siluf(v1); }
                    if (HASRES){
                        float2 rr = *reinterpret_cast<const float2*>(res + (size_t)gr*128 + cb);
                        v0 += rr.x; v1 += rr.y;
                    }
                    if (WRITEC)
                        *reinterpret_cast<float2*>(C + (size_t)gr*128 + cb) = make_float2(v0, v1);
                    if (EMIT){
                        __nv_bfloat16 h0,l0,h1,l1;
                        split_bf16(v0,h0,l0); split_bf16(v1,h1,l1);
                        __nv_bfloat162 ph; ph.x=h0; ph.y=h1;
                        __nv_bfloat162 pl; pl.x=l0; pl.y=l1;
                        *reinterpret_cast<__nv_bfloat162*>(Chi + (size_t)gr*128 + cb) = ph;
                        *reinterpret_cast<__nv_bfloat162*>(Clo + (size_t)gr*128 + cb) = pl;
                    }
                }
            }
        }
        p ^= 1;
    }
}

// ---------------- weight convert ----------------
__global__ void conv_w_kernel(const float* __restrict__ W, __nv_bfloat16* __restrict__ Wh,
                              __nv_bfloat16* __restrict__ Wl, int nmat, int Kin)
{
    int idx = blockIdx.x*blockDim.x + threadIdx.x;
    if (idx >= nmat*16384) return;
    int l = idx >> 14;
    int n = (idx >> 7) & 127;
    int k = idx & 127;
    float v = (k < Kin) ? __ldg(W + ((size_t)l*Kin + k)*128 + n) : 0.f;
    __nv_bfloat16 h, lo; split_bf16(v, h, lo);
    Wh[idx] = h; Wl[idx] = lo;
}

// ---------------- activation convert ----------------
__global__ void conv_a_kernel(const float* __restrict__ A, __nv_bfloat16* __restrict__ Ah,
                              __nv_bfloat16* __restrict__ Al, int M, int Kin)
{
    int idx = blockIdx.x*blockDim.x + threadIdx.x;
    if (idx >= M*128) return;
    int r = idx >> 7, k = idx & 127;
    float v = (k < Kin) ? __ldg(A + (size_t)r*Kin + k) : 0.f;
    __nv_bfloat16 h, l; split_bf16(v, h, l);
    Ah[idx] = h; Al[idx] = l;
}

// ---------------- scatter rows ----------------
__global__ void scatter_rows_kernel(const float* __restrict__ src, const int* __restrict__ idx,
                                    float* __restrict__ dstb, int nrows)
{
    int i = blockIdx.x*blockDim.x + threadIdx.x;
    if (i >= nrows*32) return;
    int n = i >> 5, c4 = i & 31;
    int a = __ldg(idx + n);
    float4 v = *reinterpret_cast<const float4*>(src + (size_t)n*128 + c4*4);
    float* d = dstb + (size_t)a*128 + c4*4;
    atomicAdd(d+0,v.x); atomicAdd(d+1,v.y); atomicAdd(d+2,v.z); atomicAdd(d+3,v.w);
}

// ---------------- fused rbf gate + gn pass1 ----------------
__global__ void gate_gn1_kernel(float* __restrict__ h, const float* __restrict__ rbf,
                                const float* __restrict__ W, const int* __restrict__ batch,
                                float* __restrict__ gstat)
{
    __shared__ float Ws[RBFD][DD];
    for (int t=threadIdx.x; t<RBFD*DD; t+=256) ((float*)Ws)[t] = W[t];
    __syncthreads();
    int c    = threadIdx.x & 127;
    int sub  = threadIdx.x >> 7;
    int lane = threadIdx.x & 31;
    int n0   = blockIdx.x*128;
    int nend = min(n0+128, NN);
    for (int n = n0+sub; n < nend; n += 2){
        const float* r = rbf + (size_t)n*RBFD;
        float g = 0.f;
        #pragma unroll
        for (int kk=0;kk<RBFD;kk++) g = fmaf(__ldg(r+kk), Ws[kk][c], g);
        float val = h[(size_t)n*DD+c] * g;
        h[(size_t)n*DD+c] = val;
        float ssum = val;
        #pragma unroll
        for(int o=16;o;o>>=1) ssum += __shfl_xor_sync(0xffffffffu, ssum, o);
        if (!lane){
            int gg = __ldg(batch+n);
            atomicAdd(&gstat[gg], ssum);
            if (c == 0) atomicAdd(&gstat[GG+gg], 1.f);
        }
    }
}

// ---------------- attention ----------------
__global__ void logit_kernel(const float* __restrict__ q, const float* __restrict__ k,
                             const float* __restrict__ ek, const int* __restrict__ src,
                             const int* __restrict__ dst, float* __restrict__ logit,
                             unsigned* __restrict__ mOrd)
{
    int i = blockIdx.x*blockDim.x + threadIdx.x;
    if (i >= EE*HH) return;
    int e = i >> 3, h = i & 7;
    int s = __ldg(src+e), d = __ldg(dst+e);
    const float4* qp = (const float4*)(q  + (size_t)d*DD + h*CC);
    const float4* kp = (const float4*)(k  + (size_t)s*DD + h*CC);
    const float4* ep = (const float4*)(ek + (size_t)e*DD + h*CC);
    float acc = 0.f;
    #pragma unroll
    for (int j=0;j<4;j++){
        float4 a=qp[j], b=kp[j], c=ep[j];
        acc += a.x*(b.x+c.x)+a.y*(b.y+c.y)+a.z*(b.z+c.z)+a.w*(b.w+c.w);
    }
    acc *= 0.25f;
    logit[i] = acc;
    atomicMax(&mOrd[(size_t)d*HH+h], f2o(acc));
}

__global__ void exp_kernel(const int* __restrict__ dst, float* __restrict__ logit,
                           const unsigned* __restrict__ mOrd, float* __restrict__ den)
{
    int i = blockIdx.x*blockDim.x + threadIdx.x;
    if (i >= EE*HH) return;
    int e = i >> 3, h = i & 7;
    int d = __ldg(dst+e);
    float m  = o2f(mOrd[(size_t)d*HH+h]);
    float ex = __expf(logit[i] - m);
    logit[i] = ex;
    atomicAdd(&den[(size_t)d*HH+h], ex);
}

__global__ void msg_kernel(const float* __restrict__ v, const float* __restrict__ ek,
                           const float* __restrict__ sw, const float* __restrict__ ex,
                           const float* __restrict__ den, const int* __restrict__ src,
                           const int* __restrict__ dst, float* __restrict__ hout)
{
    int i = blockIdx.x*blockDim.x + threadIdx.x;
    if (i >= EE*32) return;
    int e = i >> 5, c4 = i & 31, h = c4 >> 2;
    int sN = __ldg(src+e), dN = __ldg(dst+e);
    float alpha = __ldg(ex + (size_t)e*HH + h) / (__ldg(den + (size_t)dN*HH + h) + 1e-16f);
    float4 vv = *(const float4*)(v  + (size_t)sN*DD + c4*4);
    float4 ee = *(const float4*)(ek + (size_t)e*DD  + c4*4);
    float4 ww = *(const float4*)(sw + (size_t)e*DD  + c4*4);
    float* o = hout + (size_t)dN*DD + c4*4;
    atomicAdd(o+0, (vv.x+ee.x)*alpha*ww.x);
    atomicAdd(o+1, (vv.y+ee.y)*alpha*ww.y);
    atomicAdd(o+2, (vv.z+ee.z)*alpha*ww.z);
    atomicAdd(o+3, (vv.w+ee.w)*alpha*ww.w);
}

// ---------------- graph norm ----------------
__global__ void gn_mean_kernel(float* gstat)
{
    int g = threadIdx.x;
    if (g >= GG) return;
    float cnt = gstat[GG+g]*128.f;
    gstat[2*GG+g] = (cnt > 0.f) ? gstat[g]/cnt : 0.f;
}
__global__ void gn_pass2_kernel(const float* __restrict__ h, const int* __restrict__ batch,
                                float* __restrict__ gstat)
{
    int gi = blockIdx.x*blockDim.x + threadIdx.x;
    int n = gi >> 5, lane = gi & 31;
    if (n >= NN) return;
    int g = __ldg(batch+n);
    float mean = gstat[2*GG+g];
    float4 v = *reinterpret_cast<const float4*>(h + (size_t)n*128 + lane*4);
    float a=v.x-mean, b=v.y-mean, c=v.z-mean, d=v.w-mean;
    float s = a*a+b*b+c*c+d*d;
    #pragma unroll
    for(int o=16;o;o>>=1) s += __shfl_xor_sync(0xffffffffu, s, o);
    if (!lane) atomicAdd(&gstat[3*GG+g], s);
}
__global__ void gn_rstd_kernel(float* gstat)
{
    int g = threadIdx.x;
    if (g >= GG) return;
    float cnt = gstat[GG+g]*128.f;
    float var = (cnt > 0.f) ? gstat[3*GG+g]/cnt : 0.f;
    gstat[4*GG+g] = rsqrtf(var + 1e-8f);
}
__global__ void gn_apply_kernel(float* __restrict__ h, const int* __restrict__ batch,
                                const float* __restrict__ gstat,
                                __nv_bfloat16* __restrict__ Hh, __nv_bfloat16* __restrict__ Hl)
{
    int i = blockIdx.x*blockDim.x + threadIdx.x;
    if (i >= NN*32) return;
    int n = i >> 5;
    int g = __ldg(batch+n);
    float mean = gstat[2*GG+g], rstd = gstat[4*GG+g];
    size_t base = (size_t)n*128 + (i&31)*4;
    float4 v = *reinterpret_cast<const float4*>(h + base);
    v.x=(v.x-mean)*rstd; v.y=(v.y-mean)*rstd; v.z=(v.z-mean)*rstd; v.w=(v.w-mean)*rstd;
    *reinterpret_cast<float4*>(h + base) = v;
    __nv_bfloat16 h0,l0,h1,l1,h2,l2,h3,l3;
    split_bf16(v.x,h0,l0); split_bf16(v.y,h1,l1);
    split_bf16(v.z,h2,l2); split_bf16(v.w,h3,l3);
    __nv_bfloat162 p0; p0.x=h0; p0.y=h1;
    __nv_bfloat162 p1; p1.x=h2; p1.y=h3;
    __nv_bfloat162 q0; q0.x=l0; q0.y=l1;
    __nv_bfloat162 q1; q1.x=l2; q1.y=l3;
    *reinterpret_cast<__nv_bfloat162*>(Hh + base)     = p0;
    *reinterpret_cast<__nv_bfloat162*>(Hh + base + 2) = p1;
    *reinterpret_cast<__nv_bfloat162*>(Hl + base)     = q0;
    *reinterpret_cast<__nv_bfloat162*>(Hl + base + 2) = q1;
}

// ---------------- readout helpers ----------------
__global__ void gate_scatter_kernel(const float* __restrict__ h, const float* __restrict__ rbf,
                                    const float* __restrict__ W, const int* __restrict__ idx,
                                    float* __restrict__ atoms)
{
    __shared__ float Ws[RBFD][DD];
    for (int t=threadIdx.x; t<RBFD*DD; t+=256) ((float*)Ws)[t] = W[t];
    __syncthreads();
    int c   = threadIdx.x & 127;
    int sub = threadIdx.x >> 7;
    int n0  = blockIdx.x*128;
    int nend = min(n0+128, NN);
    for (int n = n0+sub; n < nend; n += 2){
        const float* r = rbf + (size_t)n*RBFD;
        float g = 0.f;
        #pragma unroll
        for (int kk=0;kk<RBFD;kk++) g = fmaf(__ldg(r+kk), Ws[kk][c], g);
        atomicAdd(&atoms[(size_t)__ldg(idx+n)*DD + c], h[(size_t)n*DD+c]*g);
    }
}

__global__ void readout_dot_kernel(const float* __restrict__ a2, const float* __restrict__ w3,
                                   const float* __restrict__ b3, float* __restrict__ results)
{
    int gi = blockIdx.x*blockDim.x + threadIdx.x;
    int a = gi >> 5, lane = gi & 31;
    if (a >= AA) return;
    float4 x = *(const float4*)(a2 + (size_t)a*128 + lane*4);
    float4 w = *(const float4*)(w3 + lane*4);
    float s = x.x*w.x + x.y*w.y + x.z*w.z + x.w*w.w;
    #pragma unroll
    for(int o=16;o;o>>=1) s += __shfl_xor_sync(0xffffffffu, s, o);
    if (!lane) results[a] += s + __ldg(b3);
}

__global__ void final_kernel(const float* __restrict__ results, const int* __restrict__ atom_batch,
                             float* __restrict__ out)
{
    int a = blockIdx.x*blockDim.x + threadIdx.x;
    if (a < AA) atomicAdd(&out[__ldg(atom_batch+a)], results[a]*(1.f/3.f));
}

// =======================================================================
extern "C" void kernel_launch(void* const* d_in, const int* in_sizes, int n_in,
                              void* d_out, int out_size)
{
    cudaStream_t s = 0;
    const float* x            = (const float*)d_in[0];
    const float* node_rbf     = (const float*)d_in[1];
    const float* edge_sbf     = (const float*)d_in[2];
    const int*   edge_index   = (const int*)  d_in[3];
    const int*   srcp = edge_index;
    const int*   dstp = edge_index + EE;
    const int*   pair_atom_idx= (const int*)  d_in[4];
    const int*   edge_index_0 = (const int*)  d_in[5];
    const int*   atom_batch   = (const int*)  d_in[6];
    const int*   batch        = (const int*)  d_in[7];
    const float* edgenn_w1    = (const float*)d_in[8];
    const float* edgenn_b1    = (const float*)d_in[9];
    const float* edgenn_w2    = (const float*)d_in[10];
    const float* edgenn_b2    = (const float*)d_in[11];
    const float* conv_wq      = (const float*)d_in[12];
    const float* conv_wk      = (const float*)d_in[13];
    const float* conv_wv      = (const float*)d_in[14];
    const float* conv_we      = (const float*)d_in[15];
    const float* conv_wsbf    = (const float*)d_in[16];
    const float* conv_bsbf    = (const float*)d_in[17];
    const float* conv_wrbf    = (const float*)d_in[18];
    const float* dense_w      = (const float*)d_in[19];
    const float* dense_b      = (const float*)d_in[20];
    const float* bf_w         = (const float*)d_in[21];
    const float* bf_b         = (const float*)d_in[22];
    const float* af_w         = (const float*)d_in[23];
    const float* af_b         = (const float*)d_in[24];
    const float* read_wrbf    = (const float*)d_in[25];
    const float* read_w1      = (const float*)d_in[26];
    const float* read_b1      = (const float*)d_in[27];
    const float* read_w2      = (const float*)d_in[28];
    const float* read_b2      = (const float*)d_in[29];
    const float* read_w3      = (const float*)d_in[30];
    const float* read_b3      = (const float*)d_in[31];

    cudaFuncSetAttribute((void*)gemm_bf<1,true ,false,false,true >, cudaFuncAttributeMaxDynamicSharedMemorySize, SMEM_T);
    cudaFuncSetAttribute((void*)gemm_bf<0,false,false,false,true >, cudaFuncAttributeMaxDynamicSharedMemorySize, SMEM_T);
    cudaFuncSetAttribute((void*)gemm_bf<0,false,false,true ,false>, cudaFuncAttributeMaxDynamicSharedMemorySize, SMEM_T);
    cudaFuncSetAttribute((void*)gemm_bf<1,false,false,false,true >, cudaFuncAttributeMaxDynamicSharedMemorySize, SMEM_T);
    cudaFuncSetAttribute((void*)gemm_bf<1,false,true ,false,true >, cudaFuncAttributeMaxDynamicSharedMemorySize, SMEM_T);
    cudaFuncSetAttribute((void*)gemm_bf<1,false,true ,true ,true >, cudaFuncAttributeMaxDynamicSharedMemorySize, SMEM_T);
    cudaFuncSetAttribute((void*)gemm_bf<1,false,false,true ,false>, cudaFuncAttributeMaxDynamicSharedMemorySize, SMEM_T);

    float *cur_w, *hbuf, *t1, *t2, *q, *k_, *v_, *eaA, *eaB;
    float *atoms, *atoms2, *a1, *a2, *logit, *den, *results, *gstat;
    unsigned* mOrd;
    __nv_bfloat16 *wth, *wtl, *curh, *curl, *hbh, *hbl, *t1h, *t1l, *t2h, *t2l;
    __nv_bfloat16 *qh, *ql, *eaAh, *eaAl, *eaBh, *eaBl, *sbh, *sbl;
    __nv_bfloat16 *ath, *atl, *at2h, *at2l, *a1h, *a1l;
    cudaGetSymbolAddress((void**)&cur_w,  g_cur);
    cudaGetSymbolAddress((void**)&hbuf,   g_hbuf);
    cudaGetSymbolAddress((void**)&t1,     g_t1);
    cudaGetSymbolAddress((void**)&t2,     g_t2);
    cudaGetSymbolAddress((void**)&q,      g_q);
    cudaGetSymbolAddress((void**)&k_,     g_k);
    cudaGetSymbolAddress((void**)&v_,     g_v);
    cudaGetSymbolAddress((void**)&eaA,    g_eaA);
    cudaGetSymbolAddress((void**)&eaB,    g_eaB);
    cudaGetSymbolAddress((void**)&atoms,  g_atoms);
    cudaGetSymbolAddress((void**)&atoms2, g_atoms2);
    cudaGetSymbolAddress((void**)&a1,     g_a1);
    cudaGetSymbolAddress((void**)&a2,     g_a2);
    cudaGetSymbolAddress((void**)&logit,  g_logit);
    cudaGetSymbolAddress((void**)&mOrd,   g_m);
    cudaGetSymbolAddress((void**)&den,    g_den);
    cudaGetSymbolAddress((void**)&results,g_results);
    cudaGetSymbolAddress((void**)&gstat,  g_gstat);
    cudaGetSymbolAddress((void**)&wth,  g_wth);   cudaGetSymbolAddress((void**)&wtl,  g_wtl);
    cudaGetSymbolAddress((void**)&curh, g_curh);  cudaGetSymbolAddress((void**)&curl, g_curl);
    cudaGetSymbolAddress((void**)&hbh,  g_hbh);   cudaGetSymbolAddress((void**)&hbl,  g_hbl);
    cudaGetSymbolAddress((void**)&t1h,  g_t1h);   cudaGetSymbolAddress((void**)&t1l,  g_t1l);
    cudaGetSymbolAddress((void**)&t2h,  g_t2h);   cudaGetSymbolAddress((void**)&t2l,  g_t2l);
    cudaGetSymbolAddress((void**)&qh,   g_qh);    cudaGetSymbolAddress((void**)&ql,   g_ql);
    cudaGetSymbolAddress((void**)&eaAh, g_eaAh);  cudaGetSymbolAddress((void**)&eaAl, g_eaAl);
    cudaGetSymbolAddress((void**)&eaBh, g_eaBh);  cudaGetSymbolAddress((void**)&eaBl, g_eaBl);
    cudaGetSymbolAddress((void**)&sbh,  g_sbh);   cudaGetSymbolAddress((void**)&sbl,  g_sbl);
    cudaGetSymbolAddress((void**)&ath,  g_ath);   cudaGetSymbolAddress((void**)&atl,  g_atl);
    cudaGetSymbolAddress((void**)&at2h, g_at2h);  cudaGetSymbolAddress((void**)&at2l, g_at2l);
    cudaGetSymbolAddress((void**)&a1h,  g_a1h);   cudaGetSymbolAddress((void**)&a1l,  g_a1l);

    auto WTH = [&](int slot){ return wth + (size_t)slot*16384; };
    auto WTL = [&](int slot){ return wtl + (size_t)slot*16384; };

    auto convw = [&](const float* W, int slot, int nmat, int Kin){
        conv_w_kernel<<<(nmat*16384+255)/256, 256, 0, s>>>(W, WTH(slot), WTL(slot), nmat, Kin);
    };
    convw(edgenn_w1, 0, 3, 128);
    convw(edgenn_w2, 3, 3, 128);
    convw(conv_wq,   6, 3, 128);
    convw(conv_wk,   9, 3, 128);
    convw(conv_wv,  12, 3, 128);
    convw(conv_we,  15, 3, 128);
    convw(conv_wsbf,18, 3, 112);
    convw(dense_w,  21, 3, 128);
    convw(bf_w,     24, 6, 128);
    convw(af_w,     30,12, 128);
    convw(read_w1,  42, 4, 128);
    convw(read_w2,  46, 4, 128);
    conv_a_kernel<<<(NN*128+255)/256, 256, 0, s>>>(x, curh, curl, NN, 128);
    conv_a_kernel<<<(EE*128+255)/256, 256, 0, s>>>(edge_sbf, sbh, sbl, EE, 112);

    const int GRE = 148;                 // persistent grid for E-sized GEMMs
    const int GRN = 148;                 // N-sized (469 tiles)
    const int GRA = (AA+127)/128;        // 63 tiles -> one pass

    auto readout = [&](int i, const float* h){
        cudaMemsetAsync(atoms2, 0, (size_t)AA*DD*4, s);
        gate_scatter_kernel<<<(NN+127)/128, 256, 0, s>>>(
            h, node_rbf, read_wrbf + (size_t)i*RBFD*DD, edge_index_0, atoms2);
        conv_a_kernel<<<(AA*128+255)/256, 256, 0, s>>>(atoms2, at2h, at2l, AA, 128);
        gemm_bf<1,false,false,false,true><<<GRA,256,SMEM_T,s>>>(
            at2h, at2l, WTH(42+i), WTL(42+i), read_b1 + (size_t)i*DD,
            nullptr, nullptr, nullptr, a1h, a1l, AA);
        gemm_bf<1,false,false,true,false><<<GRA,256,SMEM_T,s>>>(
            a1h, a1l, WTH(46+i), WTL(46+i), read_b2 + (size_t)i*DD,
            nullptr, nullptr, a2, nullptr, nullptr, AA);
        readout_dot_kernel<<<(AA*32+255)/256, 256, 0, s>>>(
            a2, read_w3 + (size_t)i*DD, read_b3 + i, results);
    };

    cudaMemsetAsync(results, 0, (size_t)AA*4, s);
    readout(0, x);
    const float* cur = x;
    const int GNB = (NN+127)/128;

    for (int i = 0; i < LLAYERS; i++){
        cudaMemsetAsync(atoms, 0, (size_t)AA*DD*4, s);
        scatter_rows_kernel<<<(NN*32+255)/256, 256, 0, s>>>(cur, edge_index_0, atoms, NN);
        conv_a_kernel<<<(AA*128+255)/256, 256, 0, s>>>(atoms, ath, atl, AA, 128);
        gemm_bf<1,true,false,false,true><<<GRE,256,SMEM_T,s>>>(
            ath, atl, WTH(0+i), WTL(0+i), edgenn_b1 + (size_t)i*DD,
            nullptr, pair_atom_idx, nullptr, eaAh, eaAl, EE);
        gemm_bf<0,false,false,false,true><<<GRE,256,SMEM_T,s>>>(
            eaAh, eaAl, WTH(3+i), WTL(3+i), edgenn_b2 + (size_t)i*DD,
            nullptr, nullptr, nullptr, eaBh, eaBl, EE);
        gemm_bf<0,false,false,true,false><<<GRN,256,SMEM_T,s>>>(
            curh, curl, WTH(6+i), WTL(6+i), nullptr, nullptr, nullptr, q, nullptr, nullptr, NN);
        gemm_bf<0,false,false,true,false><<<GRN,256,SMEM_T,s>>>(
            curh, curl, WTH(9+i), WTL(9+i), nullptr, nullptr, nullptr, k_, nullptr, nullptr, NN);
        gemm_bf<0,false,false,true,false><<<GRN,256,SMEM_T,s>>>(
            curh, curl, WTH(12+i), WTL(12+i), nullptr, nullptr, nullptr, v_, nullptr, nullptr, NN);
        gemm_bf<0,false,false,true,false><<<GRE,256,SMEM_T,s>>>(
            eaBh, eaBl, WTH(15+i), WTL(15+i), nullptr, nullptr, nullptr, eaA, nullptr, nullptr, EE);
        gemm_bf<0,false,false,true,false><<<GRE,256,SMEM_T,s>>>(
            sbh, sbl, WTH(18+i), WTL(18+i), conv_bsbf + (size_t)i*DD,
            nullptr, nullptr, eaB, nullptr, nullptr, EE);
        cudaMemsetAsync(mOrd, 0, (size_t)NN*HH*4, s);
        cudaMemsetAsync(den,  0, (size_t)NN*HH*4, s);
        logit_kernel<<<(EE*HH+255)/256, 256, 0, s>>>(q, k_, eaA, srcp, dstp, logit, mOrd);
        exp_kernel  <<<(EE*HH+255)/256, 256, 0, s>>>(dstp, logit, mOrd, den);
        cudaMemsetAsync(hbuf, 0, (size_t)NN*DD*4, s);
        msg_kernel  <<<(EE*32+255)/256, 256, 0, s>>>(v_, eaA, eaB, logit, den, srcp, dstp, hbuf);
        cudaMemsetAsync(gstat, 0, 5*GG*4, s);
        gate_gn1_kernel<<<GNB, 256, 0, s>>>(hbuf, node_rbf, conv_wrbf + (size_t)i*RBFD*DD, batch, gstat);
        gn_mean_kernel <<<1, GG, 0, s>>>(gstat);
        gn_pass2_kernel<<<(NN*32+255)/256, 256, 0, s>>>(hbuf, batch, gstat);
        gn_rstd_kernel <<<1, GG, 0, s>>>(gstat);
        gn_apply_kernel<<<(NN*32+255)/256, 256, 0, s>>>(hbuf, batch, gstat, hbh, hbl);
        gemm_bf<1,false,false,false,true><<<GRN,256,SMEM_T,s>>>(
            hbh, hbl, WTH(24+i*2), WTL(24+i*2), bf_b + (size_t)i*2*DD,
            nullptr, nullptr, nullptr, t1h, t1l, NN);
        gemm_bf<1,false,true,false,true><<<GRN,256,SMEM_T,s>>>(
            t1h, t1l, WTH(24+i*2+1), WTL(24+i*2+1), bf_b + (size_t)i*2*DD + DD,
            hbuf, nullptr, nullptr, t2h, t2l, NN);
        gemm_bf<1,false,true,true,true><<<GRN,256,SMEM_T,s>>>(
            t2h, t2l, WTH(21+i), WTL(21+i), dense_b + (size_t)i*DD,
            cur, nullptr, t1, t1h, t1l, NN);
        gemm_bf<1,false,false,false,true><<<GRN,256,SMEM_T,s>>>(
            t1h, t1l, WTH(30+i*4), WTL(30+i*4), af_b + (size_t)i*4*DD,
            nullptr, nullptr, nullptr, qh, ql, NN);
        gemm_bf<1,false,true,true,true><<<GRN,256,SMEM_T,s>>>(
            qh, ql, WTH(30+i*4+1), WTL(30+i*4+1), af_b + (size_t)i*4*DD + DD,
            t1, nullptr, t2, t2h, t2l, NN);
        gemm_bf<1,false,false,false,true><<<GRN,256,SMEM_T,s>>>(
            t2h, t2l, WTH(30+i*4+2), WTL(30+i*4+2), af_b + (size_t)i*4*DD + 2*DD,
            nullptr, nullptr, nullptr, qh, ql, NN);
        gemm_bf<1,false,true,true,true><<<GRN,256,SMEM_T,s>>>(
            qh, ql, WTH(30+i*4+3), WTL(30+i*4+3), af_b + (size_t)i*4*DD + 3*DD,
            t2, nullptr, cur_w, curh, curl, NN);
        cur = cur_w;
        readout(i+1, cur);
    }

    cudaMemsetAsync(d_out, 0, (size_t)GG*4, s);
    final_kernel<<<(AA+255)/256, 256, 0, s>>>(results, atom_batch, (float*)d_out);
}